// round 13
// baseline (speedup 1.0000x reference)
#include <cuda_runtime.h>
#include <cuda_fp16.h>
#include <math.h>
#include <stdint.h>

#define S_LEN   2048
#define DM      2048
#define KV_DIM  512
#define NHEADS  32
#define NKVH    8
#define HDIM    64
#define QKV_N   3072

// ---------------- fp16 hi/lo planes ----------------
__device__ __half g_xh[S_LEN * DM];                              // x hi only (A operand)
__device__ __half g_wh[QKV_N * DM],  g_wl[QKV_N * DM];           // Wq|Wk|Wv hi+lo
__device__ __half g_woh[DM * DM],    g_wol[DM * DM];             // Wo hi+lo
__device__ __half g_qkvh[S_LEN * QKV_N], g_qkvl[S_LEN * QKV_N];  // proj out hi+lo
__device__ __half g_qh[S_LEN * DM];                              // roped, scaled by 0.125*log2e
__device__ __half g_kh[S_LEN * KV_DIM], g_kl[S_LEN * KV_DIM];    // roped K hi+lo
__device__ __half g_vth[KV_DIM * S_LEN];                         // V^T hi only
__device__ __half g_ah[S_LEN * DM];                              // attn out hi
__device__ float g_rc[S_LEN * 32], g_rs[S_LEN * 32];

// ---------------- helpers ----------------
__device__ __forceinline__ uint32_t pack_h2(float e0, float e1) {
    __half2 h = __floats2half2_rn(e0, e1);
    return *(uint32_t*)&h;
}
__device__ __forceinline__ void split_h2(float x0, float x1, uint32_t& h, uint32_t& l) {
    float h0 = __half2float(__float2half_rn(x0));
    float h1 = __half2float(__float2half_rn(x1));
    h = pack_h2(h0, h1);
    l = pack_h2(x0 - h0, x1 - h1);
}
__device__ __forceinline__ void mma_f16(float* c, const uint32_t* a, const uint32_t* b) {
    asm volatile(
        "mma.sync.aligned.m16n8k16.row.col.f32.f16.f16.f32 "
        "{%0,%1,%2,%3}, {%4,%5,%6,%7}, {%8,%9}, {%0,%1,%2,%3};"
        : "+f"(c[0]), "+f"(c[1]), "+f"(c[2]), "+f"(c[3])
        : "r"(a[0]), "r"(a[1]), "r"(a[2]), "r"(a[3]), "r"(b[0]), "r"(b[1]));
}
__device__ __forceinline__ void ldsm4(uint32_t* r, uint32_t addr) {
    asm volatile("ldmatrix.sync.aligned.m8n8.x4.shared.b16 {%0,%1,%2,%3}, [%4];"
        : "=r"(r[0]), "=r"(r[1]), "=r"(r[2]), "=r"(r[3]) : "r"(addr));
}
__device__ __forceinline__ void cpa16(uint32_t dst, const void* src) {
    asm volatile("cp.async.cg.shared.global [%0], [%1], 16;" :: "r"(dst), "l"(src));
}
__device__ __forceinline__ void cp_commit() { asm volatile("cp.async.commit_group;"); }
__device__ __forceinline__ void cp_wait0()  { asm volatile("cp.async.wait_group 0;"); }
__device__ __forceinline__ void cp_wait1()  { asm volatile("cp.async.wait_group 1;"); }

// ---------------- conv (f32 -> fp16 planes) + rope table, fused ----------------
#define QX   (S_LEN * DM / 4)
#define QWQ  (DM * DM / 4)
#define QWK  (KV_DIM * DM / 4)
#define QWV  (KV_DIM * DM / 4)
#define QWO  (DM * DM / 4)
#define QTOT (QX + QWQ + QWK + QWV + QWO)
#define CONV_BLKS ((QTOT + 255) / 256)

__global__ void conv_rope(const float* __restrict__ x,  const float* __restrict__ wq,
                          const float* __restrict__ wk, const float* __restrict__ wv,
                          const float* __restrict__ wo,
                          float* __restrict__ rc, float* __restrict__ rs)
{
    int bid = blockIdx.x;
    if (bid >= CONV_BLKS) {   // rope table path
        int idx = (bid - CONV_BLKS) * 256 + threadIdx.x;
        if (idx >= S_LEN * 32) return;
        int s = idx >> 5, i = idx & 31;
        double ang = (double)s * pow(10000.0, -(double)i / 32.0);
        double sd, cd;
        sincos(ang, &sd, &cd);
        rc[idx] = (float)cd;
        rs[idx] = (float)sd;
        return;
    }
    int q = bid * 256 + threadIdx.x;
    if (q >= QTOT) return;
    const float* src;
    __half *dh, *dl;
    int lq;
    if (q < QX)                        { src = x;  dh = g_xh;  dl = nullptr; lq = q; }
    else if (q < QX + QWQ)             { src = wq; dh = g_wh;  dl = g_wl;   lq = q - QX; }
    else if (q < QX + QWQ + QWK)       { src = wk; dh = g_wh + DM * DM; dl = g_wl + DM * DM; lq = q - QX - QWQ; }
    else if (q < QX + QWQ + QWK + QWV) { src = wv; dh = g_wh + DM * DM + KV_DIM * DM; dl = g_wl + DM * DM + KV_DIM * DM; lq = q - QX - QWQ - QWK; }
    else                               { src = wo; dh = g_woh; dl = g_wol;  lq = q - QX - QWQ - QWK - QWV; }

    float4 v = ((const float4*)src)[lq];
    uint32_t h0, l0, h1, l1;
    split_h2(v.x, v.y, h0, l0);
    split_h2(v.z, v.w, h1, l1);
    ((uint32_t*)dh)[lq * 2] = h0; ((uint32_t*)dh)[lq * 2 + 1] = h1;
    if (dl) { ((uint32_t*)dl)[lq * 2] = l0; ((uint32_t*)dl)[lq * 2 + 1] = l1; }
}

// ---------------- fp16x2 GEMM (unchanged) ----------------
#define GSTR 20
#define GTILE (128 * GSTR)

__global__ __launch_bounds__(256, 2) void gemm_h2(
    const __half* __restrict__ Ah,
    const __half* __restrict__ Bh, const __half* __restrict__ Bl,
    float* __restrict__ Cf, __half* __restrict__ Ch, __half* __restrict__ Cl,
    int M, int N, int K)
{
    extern __shared__ uint32_t gsm[];

    const int t    = threadIdx.x;
    const int lane = t & 31;
    const int warp = t >> 5;
    const int wm   = warp >> 1;
    const int wn   = warp & 1;
    const int m0   = blockIdx.y * 128;
    const int n0   = blockIdx.x * 128;

    const int lrow  = t >> 1;
    const int lhalf = t & 1;

    uint32_t smBase = (uint32_t)__cvta_generic_to_shared(gsm);
    const uint32_t aHiB = 0, bHiB = GTILE * 4, bLoB = 2u * GTILE * 4;
    const uint32_t bufStride = 3u * GTILE * 4;

    const uint32_t ldDst = (uint32_t)(lrow * GSTR + lhalf * 8) * 4;

    const uint32_t aAddr = (uint32_t)((wm * 32 + (lane & 15)) * GSTR + (lane >> 4) * 4) * 4;
    const int bRow = wn * 64 + (lane & 7) + ((lane & 16) >> 1);
    const uint32_t bAddr = (uint32_t)(bRow * GSTR + ((lane & 8) ? 4 : 0)) * 4;

    const __half* aSrcH = Ah + (size_t)(m0 + lrow) * K + lhalf * 16;
    const __half* bSrcH = Bh + (size_t)(n0 + lrow) * K + lhalf * 16;
    const __half* bSrcL = Bl + (size_t)(n0 + lrow) * K + lhalf * 16;

    float acc[2][8][4];
#pragma unroll
    for (int i = 0; i < 2; ++i)
#pragma unroll
        for (int j = 0; j < 8; ++j)
#pragma unroll
            for (int k = 0; k < 4; ++k) acc[i][j][k] = 0.f;

    const int nt = K / 32;

    {
        uint32_t d = smBase + ldDst;
#pragma unroll
        for (int c = 0; c < 2; ++c) {
            cpa16(d + aHiB + c * 16, aSrcH + c * 8);
            cpa16(d + bHiB + c * 16, bSrcH + c * 8);
            cpa16(d + bLoB + c * 16, bSrcL + c * 8);
        }
        cp_commit();
    }

    for (int tt = 0; tt < nt; ++tt) {
        if (tt + 1 < nt) {
            const int k0 = (tt + 1) * 32;
            uint32_t d = smBase + (uint32_t)((tt + 1) & 1) * bufStride + ldDst;
#pragma unroll
            for (int c = 0; c < 2; ++c) {
                cpa16(d + aHiB + c * 16, aSrcH + k0 + c * 8);
                cpa16(d + bHiB + c * 16, bSrcH + k0 + c * 8);
                cpa16(d + bLoB + c * 16, bSrcL + k0 + c * 8);
            }
            cp_commit();
            cp_wait1();
        } else {
            cp_wait0();
        }
        __syncthreads();

        const uint32_t bb = smBase + (uint32_t)(tt & 1) * bufStride;

#pragma unroll
        for (int g = 0; g < 2; ++g) {
            const uint32_t gB = (uint32_t)(g * 8) * 4;
            uint32_t ah[2][4];
#pragma unroll
            for (int im = 0; im < 2; ++im)
                ldsm4(ah[im], bb + aHiB + aAddr + (uint32_t)(im * 16 * GSTR) * 4 + gB);

#pragma unroll
            for (int jj = 0; jj < 4; ++jj) {
                uint32_t bh[4], bl[4];
                const uint32_t ro = (uint32_t)(jj * 16 * GSTR) * 4;
                ldsm4(bh, bb + bHiB + bAddr + ro + gB);
                ldsm4(bl, bb + bLoB + bAddr + ro + gB);
#pragma unroll
                for (int hf = 0; hf < 2; ++hf) {
                    const int ntile = jj * 2 + hf;
#pragma unroll
                    for (int im = 0; im < 2; ++im) {
                        mma_f16(acc[im][ntile], ah[im], bl + hf * 2);
                        mma_f16(acc[im][ntile], ah[im], bh + hf * 2);
                    }
                }
            }
        }
        __syncthreads();
    }

    const int r4 = lane >> 2;
    const int c4 = lane & 3;
    const int crow0 = m0 + wm * 32 + r4;
    const int ccol0 = n0 + wn * 64 + c4 * 2;
#pragma unroll
    for (int im = 0; im < 2; ++im) {
#pragma unroll
        for (int jn = 0; jn < 8; ++jn) {
            const int row = crow0 + im * 16;
            const int col = ccol0 + jn * 8;
            float v0 = acc[im][jn][0], v1 = acc[im][jn][1];
            float v2 = acc[im][jn][2], v3 = acc[im][jn][3];
            if (Cf) {
                *(float2*)&Cf[(size_t)row * N + col]       = make_float2(v0, v1);
                *(float2*)&Cf[(size_t)(row + 8) * N + col] = make_float2(v2, v3);
            } else {
                uint32_t h, l;
                split_h2(v0, v1, h, l);
                *(uint32_t*)&Ch[(size_t)row * N + col] = h;
                *(uint32_t*)&Cl[(size_t)row * N + col] = l;
                split_h2(v2, v3, h, l);
                *(uint32_t*)&Ch[(size_t)(row + 8) * N + col] = h;
                *(uint32_t*)&Cl[(size_t)(row + 8) * N + col] = l;
            }
        }
    }
}

// ---------------- rope_qk + vt transpose, fused ----------------
#define RQ_BLKS (S_LEN * 1280 / 256)
#define VT_BLKS ((S_LEN / 32) * (KV_DIM / 32))
#define QSCALE 0.180336880111124f   /* 0.125 * log2(e) */

__global__ void ropeqk_vt(const float* __restrict__ rc, const float* __restrict__ rs)
{
    __shared__ float tile[32][33];
    int bid = blockIdx.x;
    int t = threadIdx.x;

    if (bid >= RQ_BLKS) {   // V transpose path (hi only)
        int b = bid - RQ_BLKS;
        const int s0 = (b & 63) * 32;
        const int c0 = (b >> 6) * 32;
        const int tx = t & 31, ty = t >> 5;
#pragma unroll
        for (int k = 0; k < 4; ++k) {
            int s = s0 + ty + k * 8;
            size_t src = (size_t)s * QKV_N + 2560 + c0 + tx;
            tile[ty + k * 8][tx] = __half2float(g_qkvh[src]) + __half2float(g_qkvl[src]);
        }
        __syncthreads();
#pragma unroll
        for (int k = 0; k < 4; ++k) {
            int c = c0 + ty + k * 8;
            g_vth[(size_t)c * S_LEN + s0 + tx] = __float2half_rn(tile[tx][ty + k * 8]);
        }
        return;
    }

    int idx = bid * 256 + t;
    const int per_row = 1280;
    int s = idx / per_row;
    int r = idx - s * per_row;

    if (r < 1024) {        // Q -> fp16 hi, scaled into exp2 domain
        int head = r >> 5, i = r & 31;
        int col = head * 64 + i;
        float c  = rc[(s << 5) + i];
        float sn = rs[(s << 5) + i];
        size_t b1 = (size_t)s * QKV_N + col;
        float x1 = __half2float(g_qkvh[b1])      + __half2float(g_qkvl[b1]);
        float x2 = __half2float(g_qkvh[b1 + 32]) + __half2float(g_qkvl[b1 + 32]);
        size_t d1 = (size_t)s * DM + col;
        g_qh[d1]      = __float2half_rn((x1 * c - x2 * sn) * QSCALE);
        g_qh[d1 + 32] = __float2half_rn((x2 * c + x1 * sn) * QSCALE);
    } else {               // K -> fp16 hi+lo
        int rr = r - 1024;
        int kvh = rr >> 5, i = rr & 31;
        float c  = rc[(s << 5) + i];
        float sn = rs[(s << 5) + i];
        size_t b1 = (size_t)s * QKV_N + 2048 + kvh * 64 + i;
        float x1 = __half2float(g_qkvh[b1])      + __half2float(g_qkvl[b1]);
        float x2 = __half2float(g_qkvh[b1 + 32]) + __half2float(g_qkvl[b1 + 32]);
        float y1 = x1 * c - x2 * sn;
        float y2 = x2 * c + x1 * sn;
        size_t d1 = (size_t)s * KV_DIM + kvh * 64 + i;
        __half h1 = __float2half_rn(y1), h2 = __float2half_rn(y2);
        g_kh[d1]      = h1; g_kl[d1]      = __float2half_rn(y1 - __half2float(h1));
        g_kh[d1 + 32] = h2; g_kl[d1 + 32] = __float2half_rn(y2 - __half2float(h2));
    }
}

// ---------------- Flash attention: 4 warps, 32 Q-rows per warp ----------------
#define FSTR 36

__global__ __launch_bounds__(128) void fa_tc()
{
    extern __shared__ uint32_t fsm[];

    const int t    = threadIdx.x;
    const int lane = t & 31;
    const int warp = t >> 5;          // 0..3, owns q rows [warp*32, warp*32+32)
    const int r4   = lane >> 2;
    const int c4   = lane & 3;
    const int s0   = blockIdx.x * 128;
    const int h    = blockIdx.y;
    const int kvh  = h / (NHEADS / NKVH);
    const int qcol = h * HDIM;
    const int kcol = kvh * HDIM;

    uint32_t smBase = (uint32_t)__cvta_generic_to_shared(fsm);
    const uint32_t QhB = 0;
    const uint32_t kvBase = 128u * FSTR * 4;
    const uint32_t kvStride = 3u * 64u * FSTR * 4;      // Kh|Kl|Vh per stage
    const uint32_t KhB = 0, KlB = 64u * FSTR * 4, VhB = 2u * 64u * FSTR * 4;

    const uint32_t aAddr = (uint32_t)((warp * 32 + (lane & 15)) * FSTR + (lane >> 4) * 4) * 4;
    const int bRow = (lane & 7) + ((lane & 16) >> 1);
    const uint32_t bAddr = (uint32_t)(bRow * FSTR + ((lane & 8) ? 4 : 0)) * 4;

    // group 0: Q tile — each thread loads one full row (8 chunks)
    {
        const __half* qh = g_qh + (size_t)(s0 + t) * DM + qcol;
        uint32_t d = smBase + QhB + (uint32_t)(t * FSTR) * 4;
#pragma unroll
        for (int c = 0; c < 8; ++c)
            cpa16(d + c * 16, qh + c * 8);
        cp_commit();
    }

    const int kvRow = t >> 1;          // 0..63
    const int kvCb  = (t & 1) * 4;     // 4 chunks per plane per thread
    const __half* kSrcH = g_kh + (size_t)kvRow * KV_DIM + kcol;
    const __half* kSrcL = g_kl + (size_t)kvRow * KV_DIM + kcol;
    const __half* vSrcH = g_vth + (size_t)(kcol + kvRow) * S_LEN;
    const uint32_t kvDstRow = (uint32_t)(kvRow * FSTR) * 4;

    // group 1: KV stage 0
    {
        uint32_t sb = smBase + kvBase + kvDstRow;
#pragma unroll
        for (int c = 0; c < 4; ++c) {
            cpa16(sb + KhB + (kvCb + c) * 16, kSrcH + (kvCb + c) * 8);
            cpa16(sb + KlB + (kvCb + c) * 16, kSrcL + (kvCb + c) * 8);
            cpa16(sb + VhB + (kvCb + c) * 16, vSrcH + (kvCb + c) * 8);
        }
        cp_commit();
    }

    // wait Q, hoist both m16 Q fragment sets
    uint32_t qfr[2][4][4];
    cp_wait1();
    __syncthreads();
#pragma unroll
    for (int im = 0; im < 2; ++im)
#pragma unroll
        for (int g = 0; g < 4; ++g)
            ldsm4(qfr[im][g], smBase + QhB + aAddr + (uint32_t)(im * 16 * FSTR) * 4 + (uint32_t)(g * 8) * 4);

    float o[2][8][4];
#pragma unroll
    for (int im = 0; im < 2; ++im)
#pragma unroll
        for (int j = 0; j < 8; ++j)
#pragma unroll
            for (int k = 0; k < 4; ++k) o[im][j][k] = 0.f;
    float mrow[4] = {-INFINITY, -INFINITY, -INFINITY, -INFINITY};
    float lrow[4] = {0.f, 0.f, 0.f, 0.f};

    const int NIT = S_LEN / 64;
    for (int it = 0; it < NIT; ++it) {
        if (it + 1 < NIT) {
            const int k0 = (it + 1) * 64;
            uint32_t sb = smBase + kvBase + (uint32_t)((it + 1) & 1) * kvStride + kvDstRow;
#pragma unroll
            for (int c = 0; c < 4; ++c) {
                cpa16(sb + KhB + (kvCb + c) * 16, kSrcH + (size_t)k0 * KV_DIM + (kvCb + c) * 8);
                cpa16(sb + KlB + (kvCb + c) * 16, kSrcL + (size_t)k0 * KV_DIM + (kvCb + c) * 8);
                cpa16(sb + VhB + (kvCb + c) * 16, vSrcH + k0 + (kvCb + c) * 8);
            }
            cp_commit();
            cp_wait1();
        } else {
            cp_wait0();
        }
        __syncthreads();

        const uint32_t kb = smBase + kvBase + (uint32_t)(it & 1) * kvStride;

        // ---- S = Q K^T (log2 domain), 2 m-tiles ----
        float s[2][8][4];
#pragma unroll
        for (int im = 0; im < 2; ++im)
#pragma unroll
            for (int j = 0; j < 8; ++j)
#pragma unroll
                for (int k = 0; k < 4; ++k) s[im][j][k] = 0.f;

#pragma unroll
        for (int g = 0; g < 4; ++g) {
            const uint32_t gB = (uint32_t)(g * 8) * 4;
#pragma unroll
            for (int jj = 0; jj < 4; ++jj) {
                const uint32_t ro = (uint32_t)(jj * 16 * FSTR) * 4;
                uint32_t bh[4], bl[4];
                ldsm4(bh, kb + KhB + bAddr + ro + gB);
                ldsm4(bl, kb + KlB + bAddr + ro + gB);
#pragma unroll
                for (int hf = 0; hf < 2; ++hf) {
#pragma unroll
                    for (int im = 0; im < 2; ++im) {
                        mma_f16(s[im][jj * 2 + hf], qfr[im][g], bl + hf * 2);
                        mma_f16(s[im][jj * 2 + hf], qfr[im][g], bh + hf * 2);
                    }
                }
            }
        }

        // ---- online softmax (exp2 domain), 4 row-groups ----
#pragma unroll
        for (int im = 0; im < 2; ++im) {
            float mx0 = -INFINITY, mx1 = -INFINITY;
#pragma unroll
            for (int jn = 0; jn < 8; ++jn) {
                mx0 = fmaxf(mx0, fmaxf(s[im][jn][0], s[im][jn][1]));
                mx1 = fmaxf(mx1, fmaxf(s[im][jn][2], s[im][jn][3]));
            }
            mx0 = fmaxf(mx0, __shfl_xor_sync(0xffffffffu, mx0, 1));
            mx0 = fmaxf(mx0, __shfl_xor_sync(0xffffffffu, mx0, 2));
            mx1 = fmaxf(mx1, __shfl_xor_sync(0xffffffffu, mx1, 1));
            mx1 = fmaxf(mx1, __shfl_xor_sync(0xffffffffu, mx1, 2));

            const float mn0 = fmaxf(mrow[im * 2],     mx0);
            const float mn1 = fmaxf(mrow[im * 2 + 1], mx1);
            const float a0 = exp2f(mrow[im * 2]     - mn0);
            const float a1 = exp2f(mrow[im * 2 + 1] - mn1);
            float rs0 = 0.f, rs1 = 0.f;
#pragma unroll
            for (int jn = 0; jn < 8; ++jn) {
                s[im][jn][0] = exp2f(s[im][jn][0] - mn0); rs0 += s[im][jn][0];
                s[im][jn][1] = exp2f(s[im][jn][1] - mn0); rs0 += s[im][jn][1];
                s[im][jn][2] = exp2f(s[im][jn][2] - mn1); rs1 += s[im][jn][2];
                s[im][jn][3] = exp2f(s[im][jn][3] - mn1); rs1 += s[im][jn][3];
            }
            rs0 += __shfl_xor_sync(0xffffffffu, rs0, 1);
            rs0 += __shfl_xor_sync(0xffffffffu, rs0, 2);
            rs1 += __shfl_xor_sync(0xffffffffu, rs1, 1);
            rs1 += __shfl_xor_sync(0xffffffffu, rs1, 2);

            lrow[im * 2]     = lrow[im * 2]     * a0 + rs0;
            lrow[im * 2 + 1] = lrow[im * 2 + 1] * a1 + rs1;
            mrow[im * 2]     = mn0;
            mrow[im * 2 + 1] = mn1;
#pragma unroll
            for (int jn = 0; jn < 8; ++jn) {
                o[im][jn][0] *= a0; o[im][jn][1] *= a0;
                o[im][jn][2] *= a1; o[im][jn][3] *= a1;
            }
        }

        // ---- O += P V (V hi only), 2 m-tiles share each V fragment ----
#pragma unroll
        for (int g = 0; g < 4; ++g) {
            uint32_t ph[2][4];
#pragma unroll
            for (int im = 0; im < 2; ++im) {
                ph[im][0] = pack_h2(s[im][2 * g][0],     s[im][2 * g][1]);
                ph[im][1] = pack_h2(s[im][2 * g][2],     s[im][2 * g][3]);
                ph[im][2] = pack_h2(s[im][2 * g + 1][0], s[im][2 * g + 1][1]);
                ph[im][3] = pack_h2(s[im][2 * g + 1][2], s[im][2 * g + 1][3]);
            }
            const uint32_t gB = (uint32_t)(g * 8) * 4;
#pragma unroll
            for (int jj = 0; jj < 4; ++jj) {
                const uint32_t ro = (uint32_t)(jj * 16 * FSTR) * 4;
                uint32_t vh[4];
                ldsm4(vh, kb + VhB + bAddr + ro + gB);
#pragma unroll
                for (int hf = 0; hf < 2; ++hf)
#pragma unroll
                    for (int im = 0; im < 2; ++im)
                        mma_f16(o[im][jj * 2 + hf], ph[im], vh + hf * 2);
            }
        }
        __syncthreads();
    }

    // ---- normalize + write ----
#pragma unroll
    for (int im = 0; im < 2; ++im) {
        const float inv0 = 1.0f / lrow[im * 2];
        const float inv1 = 1.0f / lrow[im * 2 + 1];
        const int row0 = s0 + warp * 32 + im * 16 + r4;
#pragma unroll
        for (int jn = 0; jn < 8; ++jn) {
            const int col = qcol + jn * 8 + c4 * 2;
            *(uint32_t*)&g_ah[(size_t)row0 * DM + col] =
                pack_h2(o[im][jn][0] * inv0, o[im][jn][1] * inv0);
            *(uint32_t*)&g_ah[(size_t)(row0 + 8) * DM + col] =
                pack_h2(o[im][jn][2] * inv1, o[im][jn][3] * inv1);
        }
    }
}

// ---------------- launch ----------------
extern "C" void kernel_launch(void* const* d_in, const int* in_sizes, int n_in,
                              void* d_out, int out_size)
{
    const float *x, *Wq, *Wk, *Wv, *Wo;
    if (in_sizes[0] == S_LEN * DM) {        // dict order [x, Wq, Wk, Wv, Wo]
        x  = (const float*)d_in[0];
        Wq = (const float*)d_in[1];
        Wk = (const float*)d_in[2];
        Wv = (const float*)d_in[3];
        Wo = (const float*)d_in[4];
    } else {                                 // sorted order [Wk, Wo, Wq, Wv, x]
        Wk = (const float*)d_in[0];
        Wo = (const float*)d_in[1];
        Wq = (const float*)d_in[2];
        Wv = (const float*)d_in[3];
        x  = (const float*)d_in[4];
    }
    float* out = (float*)d_out;

    float *rc, *rs;
    cudaGetSymbolAddress((void**)&rc, g_rc);
    cudaGetSymbolAddress((void**)&rs, g_rs);
    __half *xh, *wh, *wl, *woh, *wol, *qkvh, *qkvl, *ah;
    cudaGetSymbolAddress((void**)&xh, g_xh);
    cudaGetSymbolAddress((void**)&wh, g_wh);   cudaGetSymbolAddress((void**)&wl, g_wl);
    cudaGetSymbolAddress((void**)&woh, g_woh); cudaGetSymbolAddress((void**)&wol, g_wol);
    cudaGetSymbolAddress((void**)&qkvh, g_qkvh); cudaGetSymbolAddress((void**)&qkvl, g_qkvl);
    cudaGetSymbolAddress((void**)&ah, g_ah);

    const int gemm_smem = 2 * 3 * GTILE * sizeof(uint32_t);              // 61440
    const int fa_smem   = (128 + 2 * 3 * 64) * FSTR * sizeof(uint32_t);  // 73728
    cudaFuncSetAttribute(gemm_h2, cudaFuncAttributeMaxDynamicSharedMemorySize, gemm_smem);
    cudaFuncSetAttribute(fa_tc, cudaFuncAttributeMaxDynamicSharedMemorySize, fa_smem);

    // 1: conv + rope table (fused)
    conv_rope<<<CONV_BLKS + 256, 256>>>(x, Wq, Wk, Wv, Wo, rc, rs);

    // 2: fused QKV projection
    gemm_h2<<<dim3(QKV_N / 128, S_LEN / 128), 256, gemm_smem>>>(
        xh, wh, wl, nullptr, qkvh, qkvl, S_LEN, QKV_N, DM);

    // 3: rope_qk + V transpose (fused)
    ropeqk_vt<<<RQ_BLKS + VT_BLKS, 256>>>(rc, rs);

    // 4: flash attention  (profile slot) — 128 threads, 32 q-rows/warp
    fa_tc<<<dim3(S_LEN / 128, NHEADS), 128, fa_smem>>>();

    // 5: output projection
    gemm_h2<<<dim3(DM / 128, S_LEN / 128), 256, gemm_smem>>>(
        ah, woh, wol, out, nullptr, nullptr, S_LEN, DM, DM);
}

// round 14
// speedup vs baseline: 1.0742x; 1.0742x over previous
#include <cuda_runtime.h>
#include <cuda_fp16.h>
#include <math.h>
#include <stdint.h>

#define S_LEN   2048
#define DM      2048
#define KV_DIM  512
#define NHEADS  32
#define NKVH    8
#define HDIM    64
#define QKV_N   3072

// ---------------- fp16 hi/lo planes ----------------
__device__ __half g_xh[S_LEN * DM];                              // x hi only (A operand)
__device__ __half g_wh[QKV_N * DM],  g_wl[QKV_N * DM];           // Wq|Wk|Wv hi+lo
__device__ __half g_woh[DM * DM],    g_wol[DM * DM];             // Wo hi+lo
__device__ __half g_qkvh[S_LEN * QKV_N], g_qkvl[S_LEN * QKV_N];  // proj out hi+lo
__device__ __half g_qh[S_LEN * DM];                              // roped, scaled by 0.125*log2e
__device__ __half g_kh[S_LEN * KV_DIM], g_kl[S_LEN * KV_DIM];    // roped K hi+lo
__device__ __half g_vth[KV_DIM * S_LEN];                         // V^T hi only
__device__ __half g_ah[S_LEN * DM];                              // attn out hi
__device__ float g_rc[S_LEN * 32], g_rs[S_LEN * 32];

// ---------------- helpers ----------------
__device__ __forceinline__ uint32_t pack_h2(float e0, float e1) {
    __half2 h = __floats2half2_rn(e0, e1);
    return *(uint32_t*)&h;
}
__device__ __forceinline__ void split_h2(float x0, float x1, uint32_t& h, uint32_t& l) {
    float h0 = __half2float(__float2half_rn(x0));
    float h1 = __half2float(__float2half_rn(x1));
    h = pack_h2(h0, h1);
    l = pack_h2(x0 - h0, x1 - h1);
}
__device__ __forceinline__ void mma_f16(float* c, const uint32_t* a, const uint32_t* b) {
    asm volatile(
        "mma.sync.aligned.m16n8k16.row.col.f32.f16.f16.f32 "
        "{%0,%1,%2,%3}, {%4,%5,%6,%7}, {%8,%9}, {%0,%1,%2,%3};"
        : "+f"(c[0]), "+f"(c[1]), "+f"(c[2]), "+f"(c[3])
        : "r"(a[0]), "r"(a[1]), "r"(a[2]), "r"(a[3]), "r"(b[0]), "r"(b[1]));
}
__device__ __forceinline__ void ldsm4(uint32_t* r, uint32_t addr) {
    asm volatile("ldmatrix.sync.aligned.m8n8.x4.shared.b16 {%0,%1,%2,%3}, [%4];"
        : "=r"(r[0]), "=r"(r[1]), "=r"(r[2]), "=r"(r[3]) : "r"(addr));
}
__device__ __forceinline__ void cpa16(uint32_t dst, const void* src) {
    asm volatile("cp.async.cg.shared.global [%0], [%1], 16;" :: "r"(dst), "l"(src));
}
__device__ __forceinline__ void cp_commit() { asm volatile("cp.async.commit_group;"); }
__device__ __forceinline__ void cp_wait0()  { asm volatile("cp.async.wait_group 0;"); }
__device__ __forceinline__ void cp_wait1()  { asm volatile("cp.async.wait_group 1;"); }
__device__ __forceinline__ void cp_wait2()  { asm volatile("cp.async.wait_group 2;"); }

// ---------------- conversions (split for profile-slot targeting) ----------------
#define QX   (S_LEN * DM / 4)
#define QWQ  (DM * DM / 4)
#define QWK  (KV_DIM * DM / 4)
#define QWV  (KV_DIM * DM / 4)
#define QWO  (DM * DM / 4)
#define QWW  (QWQ + QWK + QWV + QWO)

__global__ void conv_x(const float* __restrict__ x)
{
    int lq = blockIdx.x * blockDim.x + threadIdx.x;
    if (lq >= QX) return;
    float4 v = ((const float4*)x)[lq];
    uint32_t h0, l0, h1, l1;
    split_h2(v.x, v.y, h0, l0);
    split_h2(v.z, v.w, h1, l1);
    ((uint32_t*)g_xh)[lq * 2] = h0; ((uint32_t*)g_xh)[lq * 2 + 1] = h1;
}

__global__ void conv_w(const float* __restrict__ wq, const float* __restrict__ wk,
                       const float* __restrict__ wv, const float* __restrict__ wo)
{
    int q = blockIdx.x * blockDim.x + threadIdx.x;
    if (q >= QWW) return;
    const float* src;
    __half *dh, *dl;
    int lq;
    if (q < QWQ)                  { src = wq; dh = g_wh;  dl = g_wl;  lq = q; }
    else if (q < QWQ + QWK)       { src = wk; dh = g_wh + DM * DM; dl = g_wl + DM * DM; lq = q - QWQ; }
    else if (q < QWQ + QWK + QWV) { src = wv; dh = g_wh + DM * DM + KV_DIM * DM; dl = g_wl + DM * DM + KV_DIM * DM; lq = q - QWQ - QWK; }
    else                          { src = wo; dh = g_woh; dl = g_wol; lq = q - QWQ - QWK - QWV; }

    float4 v = ((const float4*)src)[lq];
    uint32_t h0, l0, h1, l1;
    split_h2(v.x, v.y, h0, l0);
    split_h2(v.z, v.w, h1, l1);
    ((uint32_t*)dh)[lq * 2] = h0; ((uint32_t*)dh)[lq * 2 + 1] = h1;
    ((uint32_t*)dl)[lq * 2] = l0; ((uint32_t*)dl)[lq * 2 + 1] = l1;
}

__global__ void rope_table(float* __restrict__ rc, float* __restrict__ rs)
{
    int idx = blockIdx.x * blockDim.x + threadIdx.x;
    if (idx >= S_LEN * 32) return;
    int s = idx >> 5, i = idx & 31;
    double ang = (double)s * pow(10000.0, -(double)i / 32.0);
    double sd, cd;
    sincos(ang, &sd, &cd);
    rc[idx] = (float)cd;
    rs[idx] = (float)sd;
}

// ---------------- fp16x2 GEMM: 3-stage cp.async pipeline ----------------
#define GSTR 20
#define GTILE (128 * GSTR)

__global__ __launch_bounds__(256, 2) void gemm_h2(
    const __half* __restrict__ Ah,
    const __half* __restrict__ Bh, const __half* __restrict__ Bl,
    float* __restrict__ Cf, __half* __restrict__ Ch, __half* __restrict__ Cl,
    int M, int N, int K)
{
    extern __shared__ uint32_t gsm[];

    const int t    = threadIdx.x;
    const int lane = t & 31;
    const int warp = t >> 5;
    const int wm   = warp >> 1;
    const int wn   = warp & 1;
    const int m0   = blockIdx.y * 128;
    const int n0   = blockIdx.x * 128;

    const int lrow  = t >> 1;
    const int lhalf = t & 1;

    uint32_t smBase = (uint32_t)__cvta_generic_to_shared(gsm);
    const uint32_t aHiB = 0, bHiB = GTILE * 4, bLoB = 2u * GTILE * 4;
    const uint32_t bufStride = 3u * GTILE * 4;      // 30720 B per stage

    const uint32_t ldDst = (uint32_t)(lrow * GSTR + lhalf * 8) * 4;

    const uint32_t aAddr = (uint32_t)((wm * 32 + (lane & 15)) * GSTR + (lane >> 4) * 4) * 4;
    const int bRow = wn * 64 + (lane & 7) + ((lane & 16) >> 1);
    const uint32_t bAddr = (uint32_t)(bRow * GSTR + ((lane & 8) ? 4 : 0)) * 4;

    const __half* aSrcH = Ah + (size_t)(m0 + lrow) * K + lhalf * 16;
    const __half* bSrcH = Bh + (size_t)(n0 + lrow) * K + lhalf * 16;
    const __half* bSrcL = Bl + (size_t)(n0 + lrow) * K + lhalf * 16;

    float acc[2][8][4];
#pragma unroll
    for (int i = 0; i < 2; ++i)
#pragma unroll
        for (int j = 0; j < 8; ++j)
#pragma unroll
            for (int k = 0; k < 4; ++k) acc[i][j][k] = 0.f;

    const int nt = K / 32;

    // prologue: stages 0 and 1
#pragma unroll
    for (int pc = 0; pc < 2; ++pc) {
        const int k0 = pc * 32;
        uint32_t d = smBase + (uint32_t)pc * bufStride + ldDst;
#pragma unroll
        for (int c = 0; c < 2; ++c) {
            cpa16(d + aHiB + c * 16, aSrcH + k0 + c * 8);
            cpa16(d + bHiB + c * 16, bSrcH + k0 + c * 8);
            cpa16(d + bLoB + c * 16, bSrcL + k0 + c * 8);
        }
        cp_commit();
    }

    for (int tt = 0; tt < nt; ++tt) {
        if (tt + 2 < nt) {
            const int k0 = (tt + 2) * 32;
            uint32_t d = smBase + (uint32_t)((tt + 2) % 3) * bufStride + ldDst;
#pragma unroll
            for (int c = 0; c < 2; ++c) {
                cpa16(d + aHiB + c * 16, aSrcH + k0 + c * 8);
                cpa16(d + bHiB + c * 16, bSrcH + k0 + c * 8);
                cpa16(d + bLoB + c * 16, bSrcL + k0 + c * 8);
            }
            cp_commit();
            cp_wait2();
        } else if (tt + 1 < nt) {
            cp_wait1();
        } else {
            cp_wait0();
        }
        __syncthreads();

        const uint32_t bb = smBase + (uint32_t)(tt % 3) * bufStride;

#pragma unroll
        for (int g = 0; g < 2; ++g) {
            const uint32_t gB = (uint32_t)(g * 8) * 4;
            uint32_t ah[2][4];
#pragma unroll
            for (int im = 0; im < 2; ++im)
                ldsm4(ah[im], bb + aHiB + aAddr + (uint32_t)(im * 16 * GSTR) * 4 + gB);

#pragma unroll
            for (int jj = 0; jj < 4; ++jj) {
                uint32_t bh[4], bl[4];
                const uint32_t ro = (uint32_t)(jj * 16 * GSTR) * 4;
                ldsm4(bh, bb + bHiB + bAddr + ro + gB);
                ldsm4(bl, bb + bLoB + bAddr + ro + gB);
#pragma unroll
                for (int hf = 0; hf < 2; ++hf) {
                    const int ntile = jj * 2 + hf;
#pragma unroll
                    for (int im = 0; im < 2; ++im) {
                        mma_f16(acc[im][ntile], ah[im], bl + hf * 2);
                        mma_f16(acc[im][ntile], ah[im], bh + hf * 2);
                    }
                }
            }
        }
        __syncthreads();
    }

    const int r4 = lane >> 2;
    const int c4 = lane & 3;
    const int crow0 = m0 + wm * 32 + r4;
    const int ccol0 = n0 + wn * 64 + c4 * 2;
#pragma unroll
    for (int im = 0; im < 2; ++im) {
#pragma unroll
        for (int jn = 0; jn < 8; ++jn) {
            const int row = crow0 + im * 16;
            const int col = ccol0 + jn * 8;
            float v0 = acc[im][jn][0], v1 = acc[im][jn][1];
            float v2 = acc[im][jn][2], v3 = acc[im][jn][3];
            if (Cf) {
                *(float2*)&Cf[(size_t)row * N + col]       = make_float2(v0, v1);
                *(float2*)&Cf[(size_t)(row + 8) * N + col] = make_float2(v2, v3);
            } else {
                uint32_t h, l;
                split_h2(v0, v1, h, l);
                *(uint32_t*)&Ch[(size_t)row * N + col] = h;
                *(uint32_t*)&Cl[(size_t)row * N + col] = l;
                split_h2(v2, v3, h, l);
                *(uint32_t*)&Ch[(size_t)(row + 8) * N + col] = h;
                *(uint32_t*)&Cl[(size_t)(row + 8) * N + col] = l;
            }
        }
    }
}

// ---------------- rope_qk + vt transpose, fused ----------------
#define RQ_BLKS (S_LEN * 1280 / 256)
#define VT_BLKS ((S_LEN / 32) * (KV_DIM / 32))
#define QSCALE 0.180336880111124f   /* 0.125 * log2(e) */

__global__ void ropeqk_vt(const float* __restrict__ rc, const float* __restrict__ rs)
{
    __shared__ float tile[32][33];
    int bid = blockIdx.x;
    int t = threadIdx.x;

    if (bid >= RQ_BLKS) {   // V transpose path (hi only)
        int b = bid - RQ_BLKS;
        const int s0 = (b & 63) * 32;
        const int c0 = (b >> 6) * 32;
        const int tx = t & 31, ty = t >> 5;
#pragma unroll
        for (int k = 0; k < 4; ++k) {
            int s = s0 + ty + k * 8;
            size_t src = (size_t)s * QKV_N + 2560 + c0 + tx;
            tile[ty + k * 8][tx] = __half2float(g_qkvh[src]) + __half2float(g_qkvl[src]);
        }
        __syncthreads();
#pragma unroll
        for (int k = 0; k < 4; ++k) {
            int c = c0 + ty + k * 8;
            g_vth[(size_t)c * S_LEN + s0 + tx] = __float2half_rn(tile[tx][ty + k * 8]);
        }
        return;
    }

    int idx = bid * 256 + t;
    const int per_row = 1280;
    int s = idx / per_row;
    int r = idx - s * per_row;

    if (r < 1024) {        // Q -> fp16 hi, scaled into exp2 domain
        int head = r >> 5, i = r & 31;
        int col = head * 64 + i;
        float c  = rc[(s << 5) + i];
        float sn = rs[(s << 5) + i];
        size_t b1 = (size_t)s * QKV_N + col;
        float x1 = __half2float(g_qkvh[b1])      + __half2float(g_qkvl[b1]);
        float x2 = __half2float(g_qkvh[b1 + 32]) + __half2float(g_qkvl[b1 + 32]);
        size_t d1 = (size_t)s * DM + col;
        g_qh[d1]      = __float2half_rn((x1 * c - x2 * sn) * QSCALE);
        g_qh[d1 + 32] = __float2half_rn((x2 * c + x1 * sn) * QSCALE);
    } else {               // K -> fp16 hi+lo
        int rr = r - 1024;
        int kvh = rr >> 5, i = rr & 31;
        float c  = rc[(s << 5) + i];
        float sn = rs[(s << 5) + i];
        size_t b1 = (size_t)s * QKV_N + 2048 + kvh * 64 + i;
        float x1 = __half2float(g_qkvh[b1])      + __half2float(g_qkvl[b1]);
        float x2 = __half2float(g_qkvh[b1 + 32]) + __half2float(g_qkvl[b1 + 32]);
        float y1 = x1 * c - x2 * sn;
        float y2 = x2 * c + x1 * sn;
        size_t d1 = (size_t)s * KV_DIM + kvh * 64 + i;
        __half h1 = __float2half_rn(y1), h2 = __float2half_rn(y2);
        g_kh[d1]      = h1; g_kl[d1]      = __float2half_rn(y1 - __half2float(h1));
        g_kh[d1 + 32] = h2; g_kl[d1 + 32] = __float2half_rn(y2 - __half2float(h2));
    }
}

// ---------------- Flash attention (R11 version — 8 warps, 16 q-rows/warp) ----------------
#define FSTR 36

__global__ __launch_bounds__(256, 2) void fa_tc()
{
    extern __shared__ uint32_t fsm[];

    const int t    = threadIdx.x;
    const int lane = t & 31;
    const int warp = t >> 5;
    const int r4   = lane >> 2;
    const int c4   = lane & 3;
    const int s0   = blockIdx.x * 128;
    const int h    = blockIdx.y;
    const int kvh  = h / (NHEADS / NKVH);
    const int qcol = h * HDIM;
    const int kcol = kvh * HDIM;

    uint32_t smBase = (uint32_t)__cvta_generic_to_shared(fsm);
    const uint32_t QhB = 0;
    const uint32_t kvBase = 128u * FSTR * 4;
    const uint32_t kvStride = 3u * 64u * FSTR * 4;      // Kh|Kl|Vh per stage
    const uint32_t KhB = 0, KlB = 64u * FSTR * 4, VhB = 2u * 64u * FSTR * 4;

    const uint32_t aAddr = (uint32_t)((warp * 16 + (lane & 15)) * FSTR + (lane >> 4) * 4) * 4;
    const int bRow = (lane & 7) + ((lane & 16) >> 1);
    const uint32_t bAddr = (uint32_t)(bRow * FSTR + ((lane & 8) ? 4 : 0)) * 4;

    // group 0: Q tile
    {
        const int row = t >> 1;
        const int cb  = (t & 1) * 4;
        const __half* qh = g_qh + (size_t)(s0 + row) * DM + qcol;
        uint32_t d = smBase + QhB + (uint32_t)(row * FSTR) * 4;
#pragma unroll
        for (int c = 0; c < 4; ++c)
            cpa16(d + (cb + c) * 16, qh + (cb + c) * 8);
        cp_commit();
    }

    const int kvRow = t >> 2;
    const int kvCb  = (t & 3) * 2;
    const __half* kSrcH = g_kh + (size_t)kvRow * KV_DIM + kcol;
    const __half* kSrcL = g_kl + (size_t)kvRow * KV_DIM + kcol;
    const __half* vSrcH = g_vth + (size_t)(kcol + kvRow) * S_LEN;
    const uint32_t kvDstRow = (uint32_t)(kvRow * FSTR) * 4;

    // group 1: KV stage 0
    {
        uint32_t sb = smBase + kvBase + kvDstRow;
#pragma unroll
        for (int c = 0; c < 2; ++c) {
            cpa16(sb + KhB + (kvCb + c) * 16, kSrcH + (kvCb + c) * 8);
            cpa16(sb + KlB + (kvCb + c) * 16, kSrcL + (kvCb + c) * 8);
            cpa16(sb + VhB + (kvCb + c) * 16, vSrcH + (kvCb + c) * 8);
        }
        cp_commit();
    }

    // wait Q, hoist Q fragments
    uint32_t qfr[4][4];
    cp_wait1();
    __syncthreads();
#pragma unroll
    for (int g = 0; g < 4; ++g)
        ldsm4(qfr[g], smBase + QhB + aAddr + (uint32_t)(g * 8) * 4);

    float o[8][4];
#pragma unroll
    for (int j = 0; j < 8; ++j)
#pragma unroll
        for (int k = 0; k < 4; ++k) o[j][k] = 0.f;
    float mrow[2] = {-INFINITY, -INFINITY};
    float lrow[2] = {0.f, 0.f};

    const int NIT = S_LEN / 64;
    for (int it = 0; it < NIT; ++it) {
        if (it + 1 < NIT) {
            const int k0 = (it + 1) * 64;
            uint32_t sb = smBase + kvBase + (uint32_t)((it + 1) & 1) * kvStride + kvDstRow;
#pragma unroll
            for (int c = 0; c < 2; ++c) {
                cpa16(sb + KhB + (kvCb + c) * 16, kSrcH + (size_t)k0 * KV_DIM + (kvCb + c) * 8);
                cpa16(sb + KlB + (kvCb + c) * 16, kSrcL + (size_t)k0 * KV_DIM + (kvCb + c) * 8);
                cpa16(sb + VhB + (kvCb + c) * 16, vSrcH + k0 + (kvCb + c) * 8);
            }
            cp_commit();
            cp_wait1();
        } else {
            cp_wait0();
        }
        __syncthreads();

        const uint32_t kb = smBase + kvBase + (uint32_t)(it & 1) * kvStride;

        // ---- S = Q K^T (log2 domain) ----
        float s[8][4];
#pragma unroll
        for (int j = 0; j < 8; ++j)
#pragma unroll
            for (int k = 0; k < 4; ++k) s[j][k] = 0.f;

#pragma unroll
        for (int g = 0; g < 4; ++g) {
            const uint32_t gB = (uint32_t)(g * 8) * 4;
#pragma unroll
            for (int jj = 0; jj < 4; ++jj) {
                const uint32_t ro = (uint32_t)(jj * 16 * FSTR) * 4;
                uint32_t bh[4], bl[4];
                ldsm4(bh, kb + KhB + bAddr + ro + gB);
                ldsm4(bl, kb + KlB + bAddr + ro + gB);
#pragma unroll
                for (int hf = 0; hf < 2; ++hf) {
                    mma_f16(s[jj * 2 + hf], qfr[g], bl + hf * 2);
                    mma_f16(s[jj * 2 + hf], qfr[g], bh + hf * 2);
                }
            }
        }

        // ---- online softmax (exp2 domain) ----
        float mx0 = -INFINITY, mx1 = -INFINITY;
#pragma unroll
        for (int jn = 0; jn < 8; ++jn) {
            mx0 = fmaxf(mx0, fmaxf(s[jn][0], s[jn][1]));
            mx1 = fmaxf(mx1, fmaxf(s[jn][2], s[jn][3]));
        }
        mx0 = fmaxf(mx0, __shfl_xor_sync(0xffffffffu, mx0, 1));
        mx0 = fmaxf(mx0, __shfl_xor_sync(0xffffffffu, mx0, 2));
        mx1 = fmaxf(mx1, __shfl_xor_sync(0xffffffffu, mx1, 1));
        mx1 = fmaxf(mx1, __shfl_xor_sync(0xffffffffu, mx1, 2));

        const float mn0 = fmaxf(mrow[0], mx0);
        const float mn1 = fmaxf(mrow[1], mx1);
        const float a0 = exp2f(mrow[0] - mn0);
        const float a1 = exp2f(mrow[1] - mn1);
        float rs0 = 0.f, rs1 = 0.f;
#pragma unroll
        for (int jn = 0; jn < 8; ++jn) {
            s[jn][0] = exp2f(s[jn][0] - mn0); rs0 += s[jn][0];
            s[jn][1] = exp2f(s[jn][1] - mn0); rs0 += s[jn][1];
            s[jn][2] = exp2f(s[jn][2] - mn1); rs1 += s[jn][2];
            s[jn][3] = exp2f(s[jn][3] - mn1); rs1 += s[jn][3];
        }
        rs0 += __shfl_xor_sync(0xffffffffu, rs0, 1);
        rs0 += __shfl_xor_sync(0xffffffffu, rs0, 2);
        rs1 += __shfl_xor_sync(0xffffffffu, rs1, 1);
        rs1 += __shfl_xor_sync(0xffffffffu, rs1, 2);

        lrow[0] = lrow[0] * a0 + rs0;
        lrow[1] = lrow[1] * a1 + rs1;
        mrow[0] = mn0;
        mrow[1] = mn1;
#pragma unroll
        for (int jn = 0; jn < 8; ++jn) {
            o[jn][0] *= a0; o[jn][1] *= a0;
            o[jn][2] *= a1; o[jn][3] *= a1;
        }

        // ---- O += P V (V hi only) ----
#pragma unroll
        for (int g = 0; g < 4; ++g) {
            uint32_t ph[4];
            ph[0] = pack_h2(s[2 * g][0],     s[2 * g][1]);
            ph[1] = pack_h2(s[2 * g][2],     s[2 * g][3]);
            ph[2] = pack_h2(s[2 * g + 1][0], s[2 * g + 1][1]);
            ph[3] = pack_h2(s[2 * g + 1][2], s[2 * g + 1][3]);
            const uint32_t gB = (uint32_t)(g * 8) * 4;
#pragma unroll
            for (int jj = 0; jj < 4; ++jj) {
                const uint32_t ro = (uint32_t)(jj * 16 * FSTR) * 4;
                uint32_t vh[4];
                ldsm4(vh, kb + VhB + bAddr + ro + gB);
#pragma unroll
                for (int hf = 0; hf < 2; ++hf)
                    mma_f16(o[jj * 2 + hf], ph, vh + hf * 2);
            }
        }
        __syncthreads();
    }

    const float inv0 = 1.0f / lrow[0];
    const float inv1 = 1.0f / lrow[1];
    const int row0 = s0 + warp * 16 + r4;
#pragma unroll
    for (int jn = 0; jn < 8; ++jn) {
        const int col = qcol + jn * 8 + c4 * 2;
        *(uint32_t*)&g_ah[(size_t)row0 * DM + col] =
            pack_h2(o[jn][0] * inv0, o[jn][1] * inv0);
        *(uint32_t*)&g_ah[(size_t)(row0 + 8) * DM + col] =
            pack_h2(o[jn][2] * inv1, o[jn][3] * inv1);
    }
}

// ---------------- launch ----------------
extern "C" void kernel_launch(void* const* d_in, const int* in_sizes, int n_in,
                              void* d_out, int out_size)
{
    const float *x, *Wq, *Wk, *Wv, *Wo;
    if (in_sizes[0] == S_LEN * DM) {        // dict order [x, Wq, Wk, Wv, Wo]
        x  = (const float*)d_in[0];
        Wq = (const float*)d_in[1];
        Wk = (const float*)d_in[2];
        Wv = (const float*)d_in[3];
        Wo = (const float*)d_in[4];
    } else {                                 // sorted order [Wk, Wo, Wq, Wv, x]
        Wk = (const float*)d_in[0];
        Wo = (const float*)d_in[1];
        Wq = (const float*)d_in[2];
        Wv = (const float*)d_in[3];
        x  = (const float*)d_in[4];
    }
    float* out = (float*)d_out;

    float *rc, *rs;
    cudaGetSymbolAddress((void**)&rc, g_rc);
    cudaGetSymbolAddress((void**)&rs, g_rs);
    __half *xh, *wh, *wl, *woh, *wol, *qkvh, *qkvl, *ah;
    cudaGetSymbolAddress((void**)&xh, g_xh);
    cudaGetSymbolAddress((void**)&wh, g_wh);   cudaGetSymbolAddress((void**)&wl, g_wl);
    cudaGetSymbolAddress((void**)&woh, g_woh); cudaGetSymbolAddress((void**)&wol, g_wol);
    cudaGetSymbolAddress((void**)&qkvh, g_qkvh); cudaGetSymbolAddress((void**)&qkvl, g_qkvl);
    cudaGetSymbolAddress((void**)&ah, g_ah);

    const int gemm_smem = 3 * 3 * GTILE * sizeof(uint32_t);              // 92160
    const int fa_smem   = (128 + 2 * 3 * 64) * FSTR * sizeof(uint32_t);  // 73728
    cudaFuncSetAttribute(gemm_h2, cudaFuncAttributeMaxDynamicSharedMemorySize, gemm_smem);
    cudaFuncSetAttribute(fa_tc, cudaFuncAttributeMaxDynamicSharedMemorySize, fa_smem);

    // 1-3: conversions + rope table (split so gemm lands in profile slot #4)
    conv_x<<<(QX + 255) / 256, 256>>>(x);
    conv_w<<<(QWW + 255) / 256, 256>>>(Wq, Wk, Wv, Wo);
    rope_table<<<(S_LEN * 32 + 255) / 256, 256>>>(rc, rs);

    // 4: fused QKV projection (profile slot)
    gemm_h2<<<dim3(QKV_N / 128, S_LEN / 128), 256, gemm_smem>>>(
        xh, wh, wl, nullptr, qkvh, qkvl, S_LEN, QKV_N, DM);

    // 5: rope_qk + V transpose (fused)
    ropeqk_vt<<<RQ_BLKS + VT_BLKS, 256>>>(rc, rs);

    // 6: flash attention (R11 config)
    fa_tc<<<dim3(S_LEN / 128, NHEADS), 256, fa_smem>>>();

    // 7: output projection
    gemm_h2<<<dim3(DM / 128, S_LEN / 128), 256, gemm_smem>>>(
        ah, woh, wol, out, nullptr, nullptr, S_LEN, DM, DM);
}

// round 15
// speedup vs baseline: 1.2439x; 1.1579x over previous
#include <cuda_runtime.h>
#include <cuda_fp16.h>
#include <math.h>
#include <stdint.h>

#define S_LEN   2048
#define DM      2048
#define KV_DIM  512
#define NHEADS  32
#define NKVH    8
#define HDIM    64
#define QKV_N   3072

// ---------------- fp16 hi/lo planes ----------------
__device__ __half g_xh[S_LEN * DM];                              // x hi only (A operand)
__device__ __half g_wh[QKV_N * DM],  g_wl[QKV_N * DM];           // Wq|Wk|Wv hi (+lo unused for qkv)
__device__ __half g_woh[DM * DM],    g_wol[DM * DM];             // Wo hi+lo
__device__ __half g_qkvh[S_LEN * QKV_N], g_qkvl[S_LEN * QKV_N];  // proj out hi+lo
__device__ __half g_qh[S_LEN * DM];                              // roped, scaled by 0.125*log2e
__device__ __half g_kh[S_LEN * KV_DIM], g_kl[S_LEN * KV_DIM];    // roped K hi+lo
__device__ __half g_vth[KV_DIM * S_LEN];                         // V^T hi only
__device__ __half g_ah[S_LEN * DM];                              // attn out hi
__device__ float g_rc[S_LEN * 32], g_rs[S_LEN * 32];

// ---------------- helpers ----------------
__device__ __forceinline__ uint32_t pack_h2(float e0, float e1) {
    __half2 h = __floats2half2_rn(e0, e1);
    return *(uint32_t*)&h;
}
__device__ __forceinline__ void split_h2(float x0, float x1, uint32_t& h, uint32_t& l) {
    float h0 = __half2float(__float2half_rn(x0));
    float h1 = __half2float(__float2half_rn(x1));
    h = pack_h2(h0, h1);
    l = pack_h2(x0 - h0, x1 - h1);
}
__device__ __forceinline__ void mma_f16(float* c, const uint32_t* a, const uint32_t* b) {
    asm volatile(
        "mma.sync.aligned.m16n8k16.row.col.f32.f16.f16.f32 "
        "{%0,%1,%2,%3}, {%4,%5,%6,%7}, {%8,%9}, {%0,%1,%2,%3};"
        : "+f"(c[0]), "+f"(c[1]), "+f"(c[2]), "+f"(c[3])
        : "r"(a[0]), "r"(a[1]), "r"(a[2]), "r"(a[3]), "r"(b[0]), "r"(b[1]));
}
__device__ __forceinline__ void ldsm4(uint32_t* r, uint32_t addr) {
    asm volatile("ldmatrix.sync.aligned.m8n8.x4.shared.b16 {%0,%1,%2,%3}, [%4];"
        : "=r"(r[0]), "=r"(r[1]), "=r"(r[2]), "=r"(r[3]) : "r"(addr));
}
__device__ __forceinline__ void cpa16(uint32_t dst, const void* src) {
    asm volatile("cp.async.cg.shared.global [%0], [%1], 16;" :: "r"(dst), "l"(src));
}
__device__ __forceinline__ void cp_commit() { asm volatile("cp.async.commit_group;"); }
__device__ __forceinline__ void cp_wait0()  { asm volatile("cp.async.wait_group 0;"); }
__device__ __forceinline__ void cp_wait1()  { asm volatile("cp.async.wait_group 1;"); }
__device__ __forceinline__ void cp_wait2()  { asm volatile("cp.async.wait_group 2;"); }

// ---------------- conversions ----------------
#define QX   (S_LEN * DM / 4)
#define QWQ  (DM * DM / 4)
#define QWK  (KV_DIM * DM / 4)
#define QWV  (KV_DIM * DM / 4)
#define QWO  (DM * DM / 4)
#define QWW  (QWQ + QWK + QWV + QWO)

__global__ void conv_x(const float* __restrict__ x)
{
    int lq = blockIdx.x * blockDim.x + threadIdx.x;
    if (lq >= QX) return;
    float4 v = ((const float4*)x)[lq];
    uint32_t h0, l0, h1, l1;
    split_h2(v.x, v.y, h0, l0);
    split_h2(v.z, v.w, h1, l1);
    ((uint32_t*)g_xh)[lq * 2] = h0; ((uint32_t*)g_xh)[lq * 2 + 1] = h1;
}

__global__ void conv_w(const float* __restrict__ wq, const float* __restrict__ wk,
                       const float* __restrict__ wv, const float* __restrict__ wo)
{
    int q = blockIdx.x * blockDim.x + threadIdx.x;
    if (q >= QWW) return;
    const float* src;
    __half *dh, *dl;
    int lq;
    if (q < QWQ)                  { src = wq; dh = g_wh;  dl = nullptr;  lq = q; }
    else if (q < QWQ + QWK)       { src = wk; dh = g_wh + DM * DM; dl = nullptr; lq = q - QWQ; }
    else if (q < QWQ + QWK + QWV) { src = wv; dh = g_wh + DM * DM + KV_DIM * DM; dl = nullptr; lq = q - QWQ - QWK; }
    else                          { src = wo; dh = g_woh; dl = g_wol; lq = q - QWQ - QWK - QWV; }

    float4 v = ((const float4*)src)[lq];
    uint32_t h0, l0, h1, l1;
    split_h2(v.x, v.y, h0, l0);
    split_h2(v.z, v.w, h1, l1);
    ((uint32_t*)dh)[lq * 2] = h0; ((uint32_t*)dh)[lq * 2 + 1] = h1;
    if (dl) { ((uint32_t*)dl)[lq * 2] = l0; ((uint32_t*)dl)[lq * 2 + 1] = l1; }
}

__global__ void rope_table(float* __restrict__ rc, float* __restrict__ rs)
{
    int idx = blockIdx.x * blockDim.x + threadIdx.x;
    if (idx >= S_LEN * 32) return;
    int s = idx >> 5, i = idx & 31;
    double ang = (double)s * pow(10000.0, -(double)i / 32.0);
    double sd, cd;
    sincos(ang, &sd, &cd);
    rc[idx] = (float)cd;
    rs[idx] = (float)sd;
}

// ---------------- fp16 GEMM, template single/dual B pass, 3-stage cp.async ----------------
#define GSTR 20
#define GTILE (128 * GSTR)

template<bool DUAL>
__global__ __launch_bounds__(256, 2) void gemm_h2(
    const __half* __restrict__ Ah,
    const __half* __restrict__ Bh, const __half* __restrict__ Bl,
    float* __restrict__ Cf, __half* __restrict__ Ch, __half* __restrict__ Cl,
    int M, int N, int K)
{
    extern __shared__ uint32_t gsm[];

    const int t    = threadIdx.x;
    const int lane = t & 31;
    const int warp = t >> 5;
    const int wm   = warp >> 1;
    const int wn   = warp & 1;
    const int m0   = blockIdx.y * 128;
    const int n0   = blockIdx.x * 128;

    const int lrow  = t >> 1;
    const int lhalf = t & 1;

    uint32_t smBase = (uint32_t)__cvta_generic_to_shared(gsm);
    const int NTILES = DUAL ? 3 : 2;                 // aHi | bHi | (bLo)
    const uint32_t aHiB = 0, bHiB = GTILE * 4, bLoB = 2u * GTILE * 4;
    const uint32_t bufStride = (uint32_t)NTILES * GTILE * 4;

    const uint32_t ldDst = (uint32_t)(lrow * GSTR + lhalf * 8) * 4;

    const uint32_t aAddr = (uint32_t)((wm * 32 + (lane & 15)) * GSTR + (lane >> 4) * 4) * 4;
    const int bRow = wn * 64 + (lane & 7) + ((lane & 16) >> 1);
    const uint32_t bAddr = (uint32_t)(bRow * GSTR + ((lane & 8) ? 4 : 0)) * 4;

    const __half* aSrcH = Ah + (size_t)(m0 + lrow) * K + lhalf * 16;
    const __half* bSrcH = Bh + (size_t)(n0 + lrow) * K + lhalf * 16;
    const __half* bSrcL = DUAL ? (Bl + (size_t)(n0 + lrow) * K + lhalf * 16) : nullptr;

    float acc[2][8][4];
#pragma unroll
    for (int i = 0; i < 2; ++i)
#pragma unroll
        for (int j = 0; j < 8; ++j)
#pragma unroll
            for (int k = 0; k < 4; ++k) acc[i][j][k] = 0.f;

    const int nt = K / 32;

    // prologue: stages 0 and 1
#pragma unroll
    for (int pc = 0; pc < 2; ++pc) {
        const int k0 = pc * 32;
        uint32_t d = smBase + (uint32_t)pc * bufStride + ldDst;
#pragma unroll
        for (int c = 0; c < 2; ++c) {
            cpa16(d + aHiB + c * 16, aSrcH + k0 + c * 8);
            cpa16(d + bHiB + c * 16, bSrcH + k0 + c * 8);
            if (DUAL) cpa16(d + bLoB + c * 16, bSrcL + k0 + c * 8);
        }
        cp_commit();
    }

    for (int tt = 0; tt < nt; ++tt) {
        if (tt + 2 < nt) {
            const int k0 = (tt + 2) * 32;
            uint32_t d = smBase + (uint32_t)((tt + 2) % 3) * bufStride + ldDst;
#pragma unroll
            for (int c = 0; c < 2; ++c) {
                cpa16(d + aHiB + c * 16, aSrcH + k0 + c * 8);
                cpa16(d + bHiB + c * 16, bSrcH + k0 + c * 8);
                if (DUAL) cpa16(d + bLoB + c * 16, bSrcL + k0 + c * 8);
            }
            cp_commit();
            cp_wait2();
        } else if (tt + 1 < nt) {
            cp_wait1();
        } else {
            cp_wait0();
        }
        __syncthreads();

        const uint32_t bb = smBase + (uint32_t)(tt % 3) * bufStride;

#pragma unroll
        for (int g = 0; g < 2; ++g) {
            const uint32_t gB = (uint32_t)(g * 8) * 4;
            uint32_t ah[2][4];
#pragma unroll
            for (int im = 0; im < 2; ++im)
                ldsm4(ah[im], bb + aHiB + aAddr + (uint32_t)(im * 16 * GSTR) * 4 + gB);

#pragma unroll
            for (int jj = 0; jj < 4; ++jj) {
                uint32_t bh[4], bl[4];
                const uint32_t ro = (uint32_t)(jj * 16 * GSTR) * 4;
                ldsm4(bh, bb + bHiB + bAddr + ro + gB);
                if (DUAL) ldsm4(bl, bb + bLoB + bAddr + ro + gB);
#pragma unroll
                for (int hf = 0; hf < 2; ++hf) {
                    const int ntile = jj * 2 + hf;
#pragma unroll
                    for (int im = 0; im < 2; ++im) {
                        if (DUAL) mma_f16(acc[im][ntile], ah[im], bl + hf * 2);
                        mma_f16(acc[im][ntile], ah[im], bh + hf * 2);
                    }
                }
            }
        }
        __syncthreads();
    }

    const int r4 = lane >> 2;
    const int c4 = lane & 3;
    const int crow0 = m0 + wm * 32 + r4;
    const int ccol0 = n0 + wn * 64 + c4 * 2;
#pragma unroll
    for (int im = 0; im < 2; ++im) {
#pragma unroll
        for (int jn = 0; jn < 8; ++jn) {
            const int row = crow0 + im * 16;
            const int col = ccol0 + jn * 8;
            float v0 = acc[im][jn][0], v1 = acc[im][jn][1];
            float v2 = acc[im][jn][2], v3 = acc[im][jn][3];
            if (Cf) {
                *(float2*)&Cf[(size_t)row * N + col]       = make_float2(v0, v1);
                *(float2*)&Cf[(size_t)(row + 8) * N + col] = make_float2(v2, v3);
            } else {
                uint32_t h, l;
                split_h2(v0, v1, h, l);
                *(uint32_t*)&Ch[(size_t)row * N + col] = h;
                *(uint32_t*)&Cl[(size_t)row * N + col] = l;
                split_h2(v2, v3, h, l);
                *(uint32_t*)&Ch[(size_t)(row + 8) * N + col] = h;
                *(uint32_t*)&Cl[(size_t)(row + 8) * N + col] = l;
            }
        }
    }
}

// ---------------- rope_qk + vt transpose, fused ----------------
#define RQ_BLKS (S_LEN * 1280 / 256)
#define VT_BLKS ((S_LEN / 32) * (KV_DIM / 32))
#define QSCALE 0.180336880111124f   /* 0.125 * log2(e) */

__global__ void ropeqk_vt(const float* __restrict__ rc, const float* __restrict__ rs)
{
    __shared__ float tile[32][33];
    int bid = blockIdx.x;
    int t = threadIdx.x;

    if (bid >= RQ_BLKS) {   // V transpose path (hi only)
        int b = bid - RQ_BLKS;
        const int s0 = (b & 63) * 32;
        const int c0 = (b >> 6) * 32;
        const int tx = t & 31, ty = t >> 5;
#pragma unroll
        for (int k = 0; k < 4; ++k) {
            int s = s0 + ty + k * 8;
            size_t src = (size_t)s * QKV_N + 2560 + c0 + tx;
            tile[ty + k * 8][tx] = __half2float(g_qkvh[src]) + __half2float(g_qkvl[src]);
        }
        __syncthreads();
#pragma unroll
        for (int k = 0; k < 4; ++k) {
            int c = c0 + ty + k * 8;
            g_vth[(size_t)c * S_LEN + s0 + tx] = __float2half_rn(tile[tx][ty + k * 8]);
        }
        return;
    }

    int idx = bid * 256 + t;
    const int per_row = 1280;
    int s = idx / per_row;
    int r = idx - s * per_row;

    if (r < 1024) {        // Q -> fp16 hi, scaled into exp2 domain
        int head = r >> 5, i = r & 31;
        int col = head * 64 + i;
        float c  = rc[(s << 5) + i];
        float sn = rs[(s << 5) + i];
        size_t b1 = (size_t)s * QKV_N + col;
        float x1 = __half2float(g_qkvh[b1])      + __half2float(g_qkvl[b1]);
        float x2 = __half2float(g_qkvh[b1 + 32]) + __half2float(g_qkvl[b1 + 32]);
        size_t d1 = (size_t)s * DM + col;
        g_qh[d1]      = __float2half_rn((x1 * c - x2 * sn) * QSCALE);
        g_qh[d1 + 32] = __float2half_rn((x2 * c + x1 * sn) * QSCALE);
    } else {               // K -> fp16 hi+lo
        int rr = r - 1024;
        int kvh = rr >> 5, i = rr & 31;
        float c  = rc[(s << 5) + i];
        float sn = rs[(s << 5) + i];
        size_t b1 = (size_t)s * QKV_N + 2048 + kvh * 64 + i;
        float x1 = __half2float(g_qkvh[b1])      + __half2float(g_qkvl[b1]);
        float x2 = __half2float(g_qkvh[b1 + 32]) + __half2float(g_qkvl[b1 + 32]);
        float y1 = x1 * c - x2 * sn;
        float y2 = x2 * c + x1 * sn;
        size_t d1 = (size_t)s * KV_DIM + kvh * 64 + i;
        __half h1 = __float2half_rn(y1), h2 = __float2half_rn(y2);
        g_kh[d1]      = h1; g_kl[d1]      = __float2half_rn(y1 - __half2float(h1));
        g_kh[d1 + 32] = h2; g_kl[d1 + 32] = __float2half_rn(y2 - __half2float(h2));
    }
}

// ---------------- Flash attention (R11 version) ----------------
#define FSTR 36

__global__ __launch_bounds__(256, 2) void fa_tc()
{
    extern __shared__ uint32_t fsm[];

    const int t    = threadIdx.x;
    const int lane = t & 31;
    const int warp = t >> 5;
    const int r4   = lane >> 2;
    const int c4   = lane & 3;
    const int s0   = blockIdx.x * 128;
    const int h    = blockIdx.y;
    const int kvh  = h / (NHEADS / NKVH);
    const int qcol = h * HDIM;
    const int kcol = kvh * HDIM;

    uint32_t smBase = (uint32_t)__cvta_generic_to_shared(fsm);
    const uint32_t QhB = 0;
    const uint32_t kvBase = 128u * FSTR * 4;
    const uint32_t kvStride = 3u * 64u * FSTR * 4;
    const uint32_t KhB = 0, KlB = 64u * FSTR * 4, VhB = 2u * 64u * FSTR * 4;

    const uint32_t aAddr = (uint32_t)((warp * 16 + (lane & 15)) * FSTR + (lane >> 4) * 4) * 4;
    const int bRow = (lane & 7) + ((lane & 16) >> 1);
    const uint32_t bAddr = (uint32_t)(bRow * FSTR + ((lane & 8) ? 4 : 0)) * 4;

    {
        const int row = t >> 1;
        const int cb  = (t & 1) * 4;
        const __half* qh = g_qh + (size_t)(s0 + row) * DM + qcol;
        uint32_t d = smBase + QhB + (uint32_t)(row * FSTR) * 4;
#pragma unroll
        for (int c = 0; c < 4; ++c)
            cpa16(d + (cb + c) * 16, qh + (cb + c) * 8);
        cp_commit();
    }

    const int kvRow = t >> 2;
    const int kvCb  = (t & 3) * 2;
    const __half* kSrcH = g_kh + (size_t)kvRow * KV_DIM + kcol;
    const __half* kSrcL = g_kl + (size_t)kvRow * KV_DIM + kcol;
    const __half* vSrcH = g_vth + (size_t)(kcol + kvRow) * S_LEN;
    const uint32_t kvDstRow = (uint32_t)(kvRow * FSTR) * 4;

    {
        uint32_t sb = smBase + kvBase + kvDstRow;
#pragma unroll
        for (int c = 0; c < 2; ++c) {
            cpa16(sb + KhB + (kvCb + c) * 16, kSrcH + (kvCb + c) * 8);
            cpa16(sb + KlB + (kvCb + c) * 16, kSrcL + (kvCb + c) * 8);
            cpa16(sb + VhB + (kvCb + c) * 16, vSrcH + (kvCb + c) * 8);
        }
        cp_commit();
    }

    uint32_t qfr[4][4];
    cp_wait1();
    __syncthreads();
#pragma unroll
    for (int g = 0; g < 4; ++g)
        ldsm4(qfr[g], smBase + QhB + aAddr + (uint32_t)(g * 8) * 4);

    float o[8][4];
#pragma unroll
    for (int j = 0; j < 8; ++j)
#pragma unroll
        for (int k = 0; k < 4; ++k) o[j][k] = 0.f;
    float mrow[2] = {-INFINITY, -INFINITY};
    float lrow[2] = {0.f, 0.f};

    const int NIT = S_LEN / 64;
    for (int it = 0; it < NIT; ++it) {
        if (it + 1 < NIT) {
            const int k0 = (it + 1) * 64;
            uint32_t sb = smBase + kvBase + (uint32_t)((it + 1) & 1) * kvStride + kvDstRow;
#pragma unroll
            for (int c = 0; c < 2; ++c) {
                cpa16(sb + KhB + (kvCb + c) * 16, kSrcH + (size_t)k0 * KV_DIM + (kvCb + c) * 8);
                cpa16(sb + KlB + (kvCb + c) * 16, kSrcL + (size_t)k0 * KV_DIM + (kvCb + c) * 8);
                cpa16(sb + VhB + (kvCb + c) * 16, vSrcH + k0 + (kvCb + c) * 8);
            }
            cp_commit();
            cp_wait1();
        } else {
            cp_wait0();
        }
        __syncthreads();

        const uint32_t kb = smBase + kvBase + (uint32_t)(it & 1) * kvStride;

        float s[8][4];
#pragma unroll
        for (int j = 0; j < 8; ++j)
#pragma unroll
            for (int k = 0; k < 4; ++k) s[j][k] = 0.f;

#pragma unroll
        for (int g = 0; g < 4; ++g) {
            const uint32_t gB = (uint32_t)(g * 8) * 4;
#pragma unroll
            for (int jj = 0; jj < 4; ++jj) {
                const uint32_t ro = (uint32_t)(jj * 16 * FSTR) * 4;
                uint32_t bh[4], bl[4];
                ldsm4(bh, kb + KhB + bAddr + ro + gB);
                ldsm4(bl, kb + KlB + bAddr + ro + gB);
#pragma unroll
                for (int hf = 0; hf < 2; ++hf) {
                    mma_f16(s[jj * 2 + hf], qfr[g], bl + hf * 2);
                    mma_f16(s[jj * 2 + hf], qfr[g], bh + hf * 2);
                }
            }
        }

        float mx0 = -INFINITY, mx1 = -INFINITY;
#pragma unroll
        for (int jn = 0; jn < 8; ++jn) {
            mx0 = fmaxf(mx0, fmaxf(s[jn][0], s[jn][1]));
            mx1 = fmaxf(mx1, fmaxf(s[jn][2], s[jn][3]));
        }
        mx0 = fmaxf(mx0, __shfl_xor_sync(0xffffffffu, mx0, 1));
        mx0 = fmaxf(mx0, __shfl_xor_sync(0xffffffffu, mx0, 2));
        mx1 = fmaxf(mx1, __shfl_xor_sync(0xffffffffu, mx1, 1));
        mx1 = fmaxf(mx1, __shfl_xor_sync(0xffffffffu, mx1, 2));

        const float mn0 = fmaxf(mrow[0], mx0);
        const float mn1 = fmaxf(mrow[1], mx1);
        const float a0 = exp2f(mrow[0] - mn0);
        const float a1 = exp2f(mrow[1] - mn1);
        float rs0 = 0.f, rs1 = 0.f;
#pragma unroll
        for (int jn = 0; jn < 8; ++jn) {
            s[jn][0] = exp2f(s[jn][0] - mn0); rs0 += s[jn][0];
            s[jn][1] = exp2f(s[jn][1] - mn0); rs0 += s[jn][1];
            s[jn][2] = exp2f(s[jn][2] - mn1); rs1 += s[jn][2];
            s[jn][3] = exp2f(s[jn][3] - mn1); rs1 += s[jn][3];
        }
        rs0 += __shfl_xor_sync(0xffffffffu, rs0, 1);
        rs0 += __shfl_xor_sync(0xffffffffu, rs0, 2);
        rs1 += __shfl_xor_sync(0xffffffffu, rs1, 1);
        rs1 += __shfl_xor_sync(0xffffffffu, rs1, 2);

        lrow[0] = lrow[0] * a0 + rs0;
        lrow[1] = lrow[1] * a1 + rs1;
        mrow[0] = mn0;
        mrow[1] = mn1;
#pragma unroll
        for (int jn = 0; jn < 8; ++jn) {
            o[jn][0] *= a0; o[jn][1] *= a0;
            o[jn][2] *= a1; o[jn][3] *= a1;
        }

#pragma unroll
        for (int g = 0; g < 4; ++g) {
            uint32_t ph[4];
            ph[0] = pack_h2(s[2 * g][0],     s[2 * g][1]);
            ph[1] = pack_h2(s[2 * g][2],     s[2 * g][3]);
            ph[2] = pack_h2(s[2 * g + 1][0], s[2 * g + 1][1]);
            ph[3] = pack_h2(s[2 * g + 1][2], s[2 * g + 1][3]);
            const uint32_t gB = (uint32_t)(g * 8) * 4;
#pragma unroll
            for (int jj = 0; jj < 4; ++jj) {
                const uint32_t ro = (uint32_t)(jj * 16 * FSTR) * 4;
                uint32_t vh[4];
                ldsm4(vh, kb + VhB + bAddr + ro + gB);
#pragma unroll
                for (int hf = 0; hf < 2; ++hf)
                    mma_f16(o[jj * 2 + hf], ph, vh + hf * 2);
            }
        }
        __syncthreads();
    }

    const float inv0 = 1.0f / lrow[0];
    const float inv1 = 1.0f / lrow[1];
    const int row0 = s0 + warp * 16 + r4;
#pragma unroll
    for (int jn = 0; jn < 8; ++jn) {
        const int col = qcol + jn * 8 + c4 * 2;
        *(uint32_t*)&g_ah[(size_t)row0 * DM + col] =
            pack_h2(o[jn][0] * inv0, o[jn][1] * inv0);
        *(uint32_t*)&g_ah[(size_t)(row0 + 8) * DM + col] =
            pack_h2(o[jn][2] * inv1, o[jn][3] * inv1);
    }
}

// ---------------- launch ----------------
extern "C" void kernel_launch(void* const* d_in, const int* in_sizes, int n_in,
                              void* d_out, int out_size)
{
    const float *x, *Wq, *Wk, *Wv, *Wo;
    if (in_sizes[0] == S_LEN * DM) {        // dict order [x, Wq, Wk, Wv, Wo]
        x  = (const float*)d_in[0];
        Wq = (const float*)d_in[1];
        Wk = (const float*)d_in[2];
        Wv = (const float*)d_in[3];
        Wo = (const float*)d_in[4];
    } else {                                 // sorted order [Wk, Wo, Wq, Wv, x]
        Wk = (const float*)d_in[0];
        Wo = (const float*)d_in[1];
        Wq = (const float*)d_in[2];
        Wv = (const float*)d_in[3];
        x  = (const float*)d_in[4];
    }
    float* out = (float*)d_out;

    float *rc, *rs;
    cudaGetSymbolAddress((void**)&rc, g_rc);
    cudaGetSymbolAddress((void**)&rs, g_rs);
    __half *xh, *wh, *wl, *woh, *wol, *qkvh, *qkvl, *ah;
    cudaGetSymbolAddress((void**)&xh, g_xh);
    cudaGetSymbolAddress((void**)&wh, g_wh);   cudaGetSymbolAddress((void**)&wl, g_wl);
    cudaGetSymbolAddress((void**)&woh, g_woh); cudaGetSymbolAddress((void**)&wol, g_wol);
    cudaGetSymbolAddress((void**)&qkvh, g_qkvh); cudaGetSymbolAddress((void**)&qkvl, g_qkvl);
    cudaGetSymbolAddress((void**)&ah, g_ah);

    const int gemm1_smem = 3 * 2 * GTILE * sizeof(uint32_t);             // 61440 (single-pass)
    const int gemm2_smem = 3 * 3 * GTILE * sizeof(uint32_t);             // 92160 (dual-pass)
    const int fa_smem    = (128 + 2 * 3 * 64) * FSTR * sizeof(uint32_t); // 73728
    cudaFuncSetAttribute(gemm_h2<false>, cudaFuncAttributeMaxDynamicSharedMemorySize, gemm1_smem);
    cudaFuncSetAttribute(gemm_h2<true>,  cudaFuncAttributeMaxDynamicSharedMemorySize, gemm2_smem);
    cudaFuncSetAttribute(fa_tc, cudaFuncAttributeMaxDynamicSharedMemorySize, fa_smem);

    // 1-3: conversions + rope table
    conv_x<<<(QX + 255) / 256, 256>>>(x);
    conv_w<<<(QWW + 255) / 256, 256>>>(Wq, Wk, Wv, Wo);
    rope_table<<<(S_LEN * 32 + 255) / 256, 256>>>(rc, rs);

    // 4: fused QKV projection, single-pass B (profile slot)
    gemm_h2<false><<<dim3(QKV_N / 128, S_LEN / 128), 256, gemm1_smem>>>(
        xh, wh, nullptr, nullptr, qkvh, qkvl, S_LEN, QKV_N, DM);

    // 5: rope_qk + V transpose (fused)
    ropeqk_vt<<<RQ_BLKS + VT_BLKS, 256>>>(rc, rs);

    // 6: flash attention
    fa_tc<<<dim3(S_LEN / 128, NHEADS), 256, fa_smem>>>();

    // 7: output projection, dual-pass B (precision reserve)
    gemm_h2<true><<<dim3(DM / 128, S_LEN / 128), 256, gemm2_smem>>>(
        ah, woh, wol, out, nullptr, nullptr, S_LEN, DM, DM);
}

// round 16
// speedup vs baseline: 1.3509x; 1.0861x over previous
#include <cuda_runtime.h>
#include <cuda_fp16.h>
#include <math.h>
#include <stdint.h>

#define S_LEN   2048
#define DM      2048
#define KV_DIM  512
#define NHEADS  32
#define NKVH    8
#define HDIM    64
#define QKV_N   3072

// ---------------- fp16 planes ----------------
__device__ __half g_xh[S_LEN * DM];                              // x hi (A operand)
__device__ __half g_wh[QKV_N * DM];                              // Wq|Wk|Wv hi
__device__ __half g_woh[DM * DM];                                // Wo hi
__device__ __half g_qkvh[S_LEN * QKV_N], g_qkvl[S_LEN * QKV_N];  // proj out hi+lo
__device__ __half g_qh[S_LEN * DM];                              // roped, scaled by 0.125*log2e
__device__ __half g_kh[S_LEN * KV_DIM], g_kl[S_LEN * KV_DIM];    // roped K hi+lo
__device__ __half g_vth[KV_DIM * S_LEN];                         // V^T hi
__device__ __half g_ah[S_LEN * DM];                              // attn out hi
__device__ float g_rc[S_LEN * 32], g_rs[S_LEN * 32];

// ---------------- helpers ----------------
__device__ __forceinline__ uint32_t pack_h2(float e0, float e1) {
    __half2 h = __floats2half2_rn(e0, e1);
    return *(uint32_t*)&h;
}
__device__ __forceinline__ void split_h2(float x0, float x1, uint32_t& h, uint32_t& l) {
    float h0 = __half2float(__float2half_rn(x0));
    float h1 = __half2float(__float2half_rn(x1));
    h = pack_h2(h0, h1);
    l = pack_h2(x0 - h0, x1 - h1);
}
__device__ __forceinline__ void mma_f16(float* c, const uint32_t* a, const uint32_t* b) {
    asm volatile(
        "mma.sync.aligned.m16n8k16.row.col.f32.f16.f16.f32 "
        "{%0,%1,%2,%3}, {%4,%5,%6,%7}, {%8,%9}, {%0,%1,%2,%3};"
        : "+f"(c[0]), "+f"(c[1]), "+f"(c[2]), "+f"(c[3])
        : "r"(a[0]), "r"(a[1]), "r"(a[2]), "r"(a[3]), "r"(b[0]), "r"(b[1]));
}
__device__ __forceinline__ void ldsm4(uint32_t* r, uint32_t addr) {
    asm volatile("ldmatrix.sync.aligned.m8n8.x4.shared.b16 {%0,%1,%2,%3}, [%4];"
        : "=r"(r[0]), "=r"(r[1]), "=r"(r[2]), "=r"(r[3]) : "r"(addr));
}
__device__ __forceinline__ void cpa16(uint32_t dst, const void* src) {
    asm volatile("cp.async.cg.shared.global [%0], [%1], 16;" :: "r"(dst), "l"(src));
}
__device__ __forceinline__ void cp_commit() { asm volatile("cp.async.commit_group;"); }
__device__ __forceinline__ void cp_wait0()  { asm volatile("cp.async.wait_group 0;"); }
__device__ __forceinline__ void cp_wait1()  { asm volatile("cp.async.wait_group 1;"); }
__device__ __forceinline__ void cp_wait2()  { asm volatile("cp.async.wait_group 2;"); }

// ---------------- conversions ----------------
#define QX   (S_LEN * DM / 4)
#define QWQ  (DM * DM / 4)
#define QWK  (KV_DIM * DM / 4)
#define QWV  (KV_DIM * DM / 4)
#define QWO  (DM * DM / 4)
#define QWW  (QWQ + QWK + QWV + QWO)

__global__ void conv_x(const float* __restrict__ x)
{
    int lq = blockIdx.x * blockDim.x + threadIdx.x;
    if (lq >= QX) return;
    float4 v = ((const float4*)x)[lq];
    ((uint32_t*)g_xh)[lq * 2]     = pack_h2(v.x, v.y);
    ((uint32_t*)g_xh)[lq * 2 + 1] = pack_h2(v.z, v.w);
}

__global__ void conv_w(const float* __restrict__ wq, const float* __restrict__ wk,
                       const float* __restrict__ wv, const float* __restrict__ wo)
{
    int q = blockIdx.x * blockDim.x + threadIdx.x;
    if (q >= QWW) return;
    const float* src;
    __half* dh;
    int lq;
    if (q < QWQ)                  { src = wq; dh = g_wh;  lq = q; }
    else if (q < QWQ + QWK)       { src = wk; dh = g_wh + DM * DM; lq = q - QWQ; }
    else if (q < QWQ + QWK + QWV) { src = wv; dh = g_wh + DM * DM + KV_DIM * DM; lq = q - QWQ - QWK; }
    else                          { src = wo; dh = g_woh; lq = q - QWQ - QWK - QWV; }

    float4 v = ((const float4*)src)[lq];
    ((uint32_t*)dh)[lq * 2]     = pack_h2(v.x, v.y);
    ((uint32_t*)dh)[lq * 2 + 1] = pack_h2(v.z, v.w);
}

__global__ void rope_table(float* __restrict__ rc, float* __restrict__ rs)
{
    int idx = blockIdx.x * blockDim.x + threadIdx.x;
    if (idx >= S_LEN * 32) return;
    int s = idx >> 5, i = idx & 31;
    double ang = (double)s * pow(10000.0, -(double)i / 32.0);
    double sd, cd;
    sincos(ang, &sd, &cd);
    rc[idx] = (float)cd;
    rs[idx] = (float)sd;
}

// ---------------- fp16 GEMM: K-chunk 64, 3-stage cp.async, single B pass ----------------
#define GSTR 36                  // uints per smem row (32 data + 4 pad)
#define GTILE (128 * GSTR)       // 4608 uints = 18432 B

__global__ __launch_bounds__(256, 2) void gemm_h2(
    const __half* __restrict__ Ah, const __half* __restrict__ Bh,
    float* __restrict__ Cf, __half* __restrict__ Ch, __half* __restrict__ Cl,
    int M, int N, int K)
{
    extern __shared__ uint32_t gsm[];

    const int t    = threadIdx.x;
    const int lane = t & 31;
    const int warp = t >> 5;
    const int wm   = warp >> 1;
    const int wn   = warp & 1;
    const int m0   = blockIdx.y * 128;
    const int n0   = blockIdx.x * 128;

    const int lrow  = t >> 1;        // 0..127
    const int lhalf = t & 1;         // half-row select (32 halfs each)

    uint32_t smBase = (uint32_t)__cvta_generic_to_shared(gsm);
    const uint32_t aHiB = 0, bHiB = GTILE * 4;
    const uint32_t bufStride = 2u * GTILE * 4;    // 36864 B per stage

    const uint32_t ldDst = (uint32_t)(lrow * GSTR + lhalf * 16) * 4;

    const uint32_t aAddr = (uint32_t)((wm * 32 + (lane & 15)) * GSTR + (lane >> 4) * 4) * 4;
    const int bRow = wn * 64 + (lane & 7) + ((lane & 16) >> 1);
    const uint32_t bAddr = (uint32_t)(bRow * GSTR + ((lane & 8) ? 4 : 0)) * 4;

    const __half* aSrcH = Ah + (size_t)(m0 + lrow) * K + lhalf * 32;
    const __half* bSrcH = Bh + (size_t)(n0 + lrow) * K + lhalf * 32;

    float acc[2][8][4];
#pragma unroll
    for (int i = 0; i < 2; ++i)
#pragma unroll
        for (int j = 0; j < 8; ++j)
#pragma unroll
            for (int k = 0; k < 4; ++k) acc[i][j][k] = 0.f;

    const int nt = K / 64;

    // prologue: stages 0 and 1
#pragma unroll
    for (int pc = 0; pc < 2; ++pc) {
        const int k0 = pc * 64;
        uint32_t d = smBase + (uint32_t)pc * bufStride + ldDst;
#pragma unroll
        for (int c = 0; c < 4; ++c) {
            cpa16(d + aHiB + c * 16, aSrcH + k0 + c * 8);
            cpa16(d + bHiB + c * 16, bSrcH + k0 + c * 8);
        }
        cp_commit();
    }

    for (int tt = 0; tt < nt; ++tt) {
        if (tt + 2 < nt) {
            const int k0 = (tt + 2) * 64;
            uint32_t d = smBase + (uint32_t)((tt + 2) % 3) * bufStride + ldDst;
#pragma unroll
            for (int c = 0; c < 4; ++c) {
                cpa16(d + aHiB + c * 16, aSrcH + k0 + c * 8);
                cpa16(d + bHiB + c * 16, bSrcH + k0 + c * 8);
            }
            cp_commit();
            cp_wait2();
        } else if (tt + 1 < nt) {
            cp_wait1();
        } else {
            cp_wait0();
        }
        __syncthreads();

        const uint32_t bb = smBase + (uint32_t)(tt % 3) * bufStride;

#pragma unroll
        for (int g = 0; g < 4; ++g) {         // four k16 groups per 64-chunk
            const uint32_t gB = (uint32_t)(g * 8) * 4;
            uint32_t ah[2][4];
#pragma unroll
            for (int im = 0; im < 2; ++im)
                ldsm4(ah[im], bb + aHiB + aAddr + (uint32_t)(im * 16 * GSTR) * 4 + gB);

#pragma unroll
            for (int jj = 0; jj < 4; ++jj) {
                uint32_t bh[4];
                const uint32_t ro = (uint32_t)(jj * 16 * GSTR) * 4;
                ldsm4(bh, bb + bHiB + bAddr + ro + gB);
#pragma unroll
                for (int hf = 0; hf < 2; ++hf) {
                    const int ntile = jj * 2 + hf;
#pragma unroll
                    for (int im = 0; im < 2; ++im)
                        mma_f16(acc[im][ntile], ah[im], bh + hf * 2);
                }
            }
        }
        __syncthreads();
    }

    const int r4 = lane >> 2;
    const int c4 = lane & 3;
    const int crow0 = m0 + wm * 32 + r4;
    const int ccol0 = n0 + wn * 64 + c4 * 2;
#pragma unroll
    for (int im = 0; im < 2; ++im) {
#pragma unroll
        for (int jn = 0; jn < 8; ++jn) {
            const int row = crow0 + im * 16;
            const int col = ccol0 + jn * 8;
            float v0 = acc[im][jn][0], v1 = acc[im][jn][1];
            float v2 = acc[im][jn][2], v3 = acc[im][jn][3];
            if (Cf) {
                *(float2*)&Cf[(size_t)row * N + col]       = make_float2(v0, v1);
                *(float2*)&Cf[(size_t)(row + 8) * N + col] = make_float2(v2, v3);
            } else {
                uint32_t h, l;
                split_h2(v0, v1, h, l);
                *(uint32_t*)&Ch[(size_t)row * N + col] = h;
                *(uint32_t*)&Cl[(size_t)row * N + col] = l;
                split_h2(v2, v3, h, l);
                *(uint32_t*)&Ch[(size_t)(row + 8) * N + col] = h;
                *(uint32_t*)&Cl[(size_t)(row + 8) * N + col] = l;
            }
        }
    }
}

// ---------------- rope_qk + vt transpose, fused ----------------
#define RQ_BLKS (S_LEN * 1280 / 256)
#define VT_BLKS ((S_LEN / 32) * (KV_DIM / 32))
#define QSCALE 0.180336880111124f   /* 0.125 * log2(e) */

__global__ void ropeqk_vt(const float* __restrict__ rc, const float* __restrict__ rs)
{
    __shared__ float tile[32][33];
    int bid = blockIdx.x;
    int t = threadIdx.x;

    if (bid >= RQ_BLKS) {   // V transpose path (hi only)
        int b = bid - RQ_BLKS;
        const int s0 = (b & 63) * 32;
        const int c0 = (b >> 6) * 32;
        const int tx = t & 31, ty = t >> 5;
#pragma unroll
        for (int k = 0; k < 4; ++k) {
            int s = s0 + ty + k * 8;
            size_t src = (size_t)s * QKV_N + 2560 + c0 + tx;
            tile[ty + k * 8][tx] = __half2float(g_qkvh[src]) + __half2float(g_qkvl[src]);
        }
        __syncthreads();
#pragma unroll
        for (int k = 0; k < 4; ++k) {
            int c = c0 + ty + k * 8;
            g_vth[(size_t)c * S_LEN + s0 + tx] = __float2half_rn(tile[tx][ty + k * 8]);
        }
        return;
    }

    int idx = bid * 256 + t;
    const int per_row = 1280;
    int s = idx / per_row;
    int r = idx - s * per_row;

    if (r < 1024) {        // Q -> fp16 hi, scaled into exp2 domain
        int head = r >> 5, i = r & 31;
        int col = head * 64 + i;
        float c  = rc[(s << 5) + i];
        float sn = rs[(s << 5) + i];
        size_t b1 = (size_t)s * QKV_N + col;
        float x1 = __half2float(g_qkvh[b1])      + __half2float(g_qkvl[b1]);
        float x2 = __half2float(g_qkvh[b1 + 32]) + __half2float(g_qkvl[b1 + 32]);
        size_t d1 = (size_t)s * DM + col;
        g_qh[d1]      = __float2half_rn((x1 * c - x2 * sn) * QSCALE);
        g_qh[d1 + 32] = __float2half_rn((x2 * c + x1 * sn) * QSCALE);
    } else {               // K -> fp16 hi+lo
        int rr = r - 1024;
        int kvh = rr >> 5, i = rr & 31;
        float c  = rc[(s << 5) + i];
        float sn = rs[(s << 5) + i];
        size_t b1 = (size_t)s * QKV_N + 2048 + kvh * 64 + i;
        float x1 = __half2float(g_qkvh[b1])      + __half2float(g_qkvl[b1]);
        float x2 = __half2float(g_qkvh[b1 + 32]) + __half2float(g_qkvl[b1 + 32]);
        float y1 = x1 * c - x2 * sn;
        float y2 = x2 * c + x1 * sn;
        size_t d1 = (size_t)s * KV_DIM + kvh * 64 + i;
        __half h1 = __float2half_rn(y1), h2 = __float2half_rn(y2);
        g_kh[d1]      = h1; g_kl[d1]      = __float2half_rn(y1 - __half2float(h1));
        g_kh[d1 + 32] = h2; g_kl[d1 + 32] = __float2half_rn(y2 - __half2float(h2));
    }
}

// ---------------- Flash attention (R11 version, unchanged) ----------------
#define FSTR 36

__global__ __launch_bounds__(256, 2) void fa_tc()
{
    extern __shared__ uint32_t fsm[];

    const int t    = threadIdx.x;
    const int lane = t & 31;
    const int warp = t >> 5;
    const int r4   = lane >> 2;
    const int c4   = lane & 3;
    const int s0   = blockIdx.x * 128;
    const int h    = blockIdx.y;
    const int kvh  = h / (NHEADS / NKVH);
    const int qcol = h * HDIM;
    const int kcol = kvh * HDIM;

    uint32_t smBase = (uint32_t)__cvta_generic_to_shared(fsm);
    const uint32_t QhB = 0;
    const uint32_t kvBase = 128u * FSTR * 4;
    const uint32_t kvStride = 3u * 64u * FSTR * 4;
    const uint32_t KhB = 0, KlB = 64u * FSTR * 4, VhB = 2u * 64u * FSTR * 4;

    const uint32_t aAddr = (uint32_t)((warp * 16 + (lane & 15)) * FSTR + (lane >> 4) * 4) * 4;
    const int bRow = (lane & 7) + ((lane & 16) >> 1);
    const uint32_t bAddr = (uint32_t)(bRow * FSTR + ((lane & 8) ? 4 : 0)) * 4;

    {
        const int row = t >> 1;
        const int cb  = (t & 1) * 4;
        const __half* qh = g_qh + (size_t)(s0 + row) * DM + qcol;
        uint32_t d = smBase + QhB + (uint32_t)(row * FSTR) * 4;
#pragma unroll
        for (int c = 0; c < 4; ++c)
            cpa16(d + (cb + c) * 16, qh + (cb + c) * 8);
        cp_commit();
    }

    const int kvRow = t >> 2;
    const int kvCb  = (t & 3) * 2;
    const __half* kSrcH = g_kh + (size_t)kvRow * KV_DIM + kcol;
    const __half* kSrcL = g_kl + (size_t)kvRow * KV_DIM + kcol;
    const __half* vSrcH = g_vth + (size_t)(kcol + kvRow) * S_LEN;
    const uint32_t kvDstRow = (uint32_t)(kvRow * FSTR) * 4;

    {
        uint32_t sb = smBase + kvBase + kvDstRow;
#pragma unroll
        for (int c = 0; c < 2; ++c) {
            cpa16(sb + KhB + (kvCb + c) * 16, kSrcH + (kvCb + c) * 8);
            cpa16(sb + KlB + (kvCb + c) * 16, kSrcL + (kvCb + c) * 8);
            cpa16(sb + VhB + (kvCb + c) * 16, vSrcH + (kvCb + c) * 8);
        }
        cp_commit();
    }

    uint32_t qfr[4][4];
    cp_wait1();
    __syncthreads();
#pragma unroll
    for (int g = 0; g < 4; ++g)
        ldsm4(qfr[g], smBase + QhB + aAddr + (uint32_t)(g * 8) * 4);

    float o[8][4];
#pragma unroll
    for (int j = 0; j < 8; ++j)
#pragma unroll
        for (int k = 0; k < 4; ++k) o[j][k] = 0.f;
    float mrow[2] = {-INFINITY, -INFINITY};
    float lrow[2] = {0.f, 0.f};

    const int NIT = S_LEN / 64;
    for (int it = 0; it < NIT; ++it) {
        if (it + 1 < NIT) {
            const int k0 = (it + 1) * 64;
            uint32_t sb = smBase + kvBase + (uint32_t)((it + 1) & 1) * kvStride + kvDstRow;
#pragma unroll
            for (int c = 0; c < 2; ++c) {
                cpa16(sb + KhB + (kvCb + c) * 16, kSrcH + (size_t)k0 * KV_DIM + (kvCb + c) * 8);
                cpa16(sb + KlB + (kvCb + c) * 16, kSrcL + (size_t)k0 * KV_DIM + (kvCb + c) * 8);
                cpa16(sb + VhB + (kvCb + c) * 16, vSrcH + k0 + (kvCb + c) * 8);
            }
            cp_commit();
            cp_wait1();
        } else {
            cp_wait0();
        }
        __syncthreads();

        const uint32_t kb = smBase + kvBase + (uint32_t)(it & 1) * kvStride;

        float s[8][4];
#pragma unroll
        for (int j = 0; j < 8; ++j)
#pragma unroll
            for (int k = 0; k < 4; ++k) s[j][k] = 0.f;

#pragma unroll
        for (int g = 0; g < 4; ++g) {
            const uint32_t gB = (uint32_t)(g * 8) * 4;
#pragma unroll
            for (int jj = 0; jj < 4; ++jj) {
                const uint32_t ro = (uint32_t)(jj * 16 * FSTR) * 4;
                uint32_t bh[4], bl[4];
                ldsm4(bh, kb + KhB + bAddr + ro + gB);
                ldsm4(bl, kb + KlB + bAddr + ro + gB);
#pragma unroll
                for (int hf = 0; hf < 2; ++hf) {
                    mma_f16(s[jj * 2 + hf], qfr[g], bl + hf * 2);
                    mma_f16(s[jj * 2 + hf], qfr[g], bh + hf * 2);
                }
            }
        }

        float mx0 = -INFINITY, mx1 = -INFINITY;
#pragma unroll
        for (int jn = 0; jn < 8; ++jn) {
            mx0 = fmaxf(mx0, fmaxf(s[jn][0], s[jn][1]));
            mx1 = fmaxf(mx1, fmaxf(s[jn][2], s[jn][3]));
        }
        mx0 = fmaxf(mx0, __shfl_xor_sync(0xffffffffu, mx0, 1));
        mx0 = fmaxf(mx0, __shfl_xor_sync(0xffffffffu, mx0, 2));
        mx1 = fmaxf(mx1, __shfl_xor_sync(0xffffffffu, mx1, 1));
        mx1 = fmaxf(mx1, __shfl_xor_sync(0xffffffffu, mx1, 2));

        const float mn0 = fmaxf(mrow[0], mx0);
        const float mn1 = fmaxf(mrow[1], mx1);
        const float a0 = exp2f(mrow[0] - mn0);
        const float a1 = exp2f(mrow[1] - mn1);
        float rs0 = 0.f, rs1 = 0.f;
#pragma unroll
        for (int jn = 0; jn < 8; ++jn) {
            s[jn][0] = exp2f(s[jn][0] - mn0); rs0 += s[jn][0];
            s[jn][1] = exp2f(s[jn][1] - mn0); rs0 += s[jn][1];
            s[jn][2] = exp2f(s[jn][2] - mn1); rs1 += s[jn][2];
            s[jn][3] = exp2f(s[jn][3] - mn1); rs1 += s[jn][3];
        }
        rs0 += __shfl_xor_sync(0xffffffffu, rs0, 1);
        rs0 += __shfl_xor_sync(0xffffffffu, rs0, 2);
        rs1 += __shfl_xor_sync(0xffffffffu, rs1, 1);
        rs1 += __shfl_xor_sync(0xffffffffu, rs1, 2);

        lrow[0] = lrow[0] * a0 + rs0;
        lrow[1] = lrow[1] * a1 + rs1;
        mrow[0] = mn0;
        mrow[1] = mn1;
#pragma unroll
        for (int jn = 0; jn < 8; ++jn) {
            o[jn][0] *= a0; o[jn][1] *= a0;
            o[jn][2] *= a1; o[jn][3] *= a1;
        }

#pragma unroll
        for (int g = 0; g < 4; ++g) {
            uint32_t ph[4];
            ph[0] = pack_h2(s[2 * g][0],     s[2 * g][1]);
            ph[1] = pack_h2(s[2 * g][2],     s[2 * g][3]);
            ph[2] = pack_h2(s[2 * g + 1][0], s[2 * g + 1][1]);
            ph[3] = pack_h2(s[2 * g + 1][2], s[2 * g + 1][3]);
            const uint32_t gB = (uint32_t)(g * 8) * 4;
#pragma unroll
            for (int jj = 0; jj < 4; ++jj) {
                const uint32_t ro = (uint32_t)(jj * 16 * FSTR) * 4;
                uint32_t vh[4];
                ldsm4(vh, kb + VhB + bAddr + ro + gB);
#pragma unroll
                for (int hf = 0; hf < 2; ++hf)
                    mma_f16(o[jj * 2 + hf], ph, vh + hf * 2);
            }
        }
        __syncthreads();
    }

    const float inv0 = 1.0f / lrow[0];
    const float inv1 = 1.0f / lrow[1];
    const int row0 = s0 + warp * 16 + r4;
#pragma unroll
    for (int jn = 0; jn < 8; ++jn) {
        const int col = qcol + jn * 8 + c4 * 2;
        *(uint32_t*)&g_ah[(size_t)row0 * DM + col] =
            pack_h2(o[jn][0] * inv0, o[jn][1] * inv0);
        *(uint32_t*)&g_ah[(size_t)(row0 + 8) * DM + col] =
            pack_h2(o[jn][2] * inv1, o[jn][3] * inv1);
    }
}

// ---------------- launch ----------------
extern "C" void kernel_launch(void* const* d_in, const int* in_sizes, int n_in,
                              void* d_out, int out_size)
{
    const float *x, *Wq, *Wk, *Wv, *Wo;
    if (in_sizes[0] == S_LEN * DM) {        // dict order [x, Wq, Wk, Wv, Wo]
        x  = (const float*)d_in[0];
        Wq = (const float*)d_in[1];
        Wk = (const float*)d_in[2];
        Wv = (const float*)d_in[3];
        Wo = (const float*)d_in[4];
    } else {                                 // sorted order [Wk, Wo, Wq, Wv, x]
        Wk = (const float*)d_in[0];
        Wo = (const float*)d_in[1];
        Wq = (const float*)d_in[2];
        Wv = (const float*)d_in[3];
        x  = (const float*)d_in[4];
    }
    float* out = (float*)d_out;

    float *rc, *rs;
    cudaGetSymbolAddress((void**)&rc, g_rc);
    cudaGetSymbolAddress((void**)&rs, g_rs);
    __half *xh, *wh, *woh, *qkvh, *qkvl, *ah;
    cudaGetSymbolAddress((void**)&xh, g_xh);
    cudaGetSymbolAddress((void**)&wh, g_wh);
    cudaGetSymbolAddress((void**)&woh, g_woh);
    cudaGetSymbolAddress((void**)&qkvh, g_qkvh); cudaGetSymbolAddress((void**)&qkvl, g_qkvl);
    cudaGetSymbolAddress((void**)&ah, g_ah);

    const int gemm_smem = 3 * 2 * GTILE * sizeof(uint32_t);              // 110592
    const int fa_smem   = (128 + 2 * 3 * 64) * FSTR * sizeof(uint32_t);  // 73728
    cudaFuncSetAttribute(gemm_h2, cudaFuncAttributeMaxDynamicSharedMemorySize, gemm_smem);
    cudaFuncSetAttribute(fa_tc, cudaFuncAttributeMaxDynamicSharedMemorySize, fa_smem);

    // 1-3: conversions + rope table
    conv_x<<<(QX + 255) / 256, 256>>>(x);
    conv_w<<<(QWW + 255) / 256, 256>>>(Wq, Wk, Wv, Wo);
    rope_table<<<(S_LEN * 32 + 255) / 256, 256>>>(rc, rs);

    // 4: fused QKV projection (profile slot)
    gemm_h2<<<dim3(QKV_N / 128, S_LEN / 128), 256, gemm_smem>>>(
        xh, wh, nullptr, qkvh, qkvl, S_LEN, QKV_N, DM);

    // 5: rope_qk + V transpose (fused)
    ropeqk_vt<<<RQ_BLKS + VT_BLKS, 256>>>(rc, rs);

    // 6: flash attention
    fa_tc<<<dim3(S_LEN / 128, NHEADS), 256, fa_smem>>>();

    // 7: output projection (single-pass)
    gemm_h2<<<dim3(DM / 128, S_LEN / 128), 256, gemm_smem>>>(
        ah, woh, out, nullptr, nullptr, S_LEN, DM, DM);
}